// round 7
// baseline (speedup 1.0000x reference)
#include <cuda_runtime.h>
#include <math.h>
#include <stdint.h>

#define B_    64
#define SEQ   257
#define S_    256
#define D_    768
#define F_    3072
#define HEADS 12
#define DKH   64
#define ROWS  (B_*SEQ)     // 16448
#define BSR   (B_*S_)      // 16384

// ---------------- scratch ----------------
__device__ float g_h[(size_t)ROWS*D_];
__device__ float g_q[(size_t)ROWS*D_];
__device__ float g_k[(size_t)ROWS*D_];
__device__ float g_v[(size_t)ROWS*D_];
__device__ float g_o[(size_t)ROWS*D_];
__device__ float g_t[(size_t)ROWS*D_];
__device__ float g_f[(size_t)ROWS*F_];
__device__ float g_wr[14155776];   // tf32-RNA pre-rounded weights

#define RQ_OFF 0
#define RK_OFF 1179648
#define RV_OFF 2359296
#define RO_OFF 3538944
#define R1_OFF 4718592
#define R2_OFF 9437184

__device__ __forceinline__ float gelu_f(float x) {
    float x3 = x * x * x;
    float t = tanhf(0.7978845608028654f * (x + 0.044715f * x3));
    return 0.5f * x * (1.0f + t);
}

__device__ __forceinline__ uint32_t f2tf(float x) {
    uint32_t u;
    asm("cvt.rna.tf32.f32 %0, %1;" : "=r"(u) : "f"(x));
    return u;
}

// ---------------- weight pre-round ----------------
__global__ void rnd_kernel(const float* __restrict__ src, float* __restrict__ dst, int n4)
{
    int i = blockIdx.x * 256 + threadIdx.x;
    if (i < n4) {
        float4 v = ((const float4*)src)[i];
        uint4 u = make_uint4(f2tf(v.x), f2tf(v.y), f2tf(v.z), f2tf(v.w));
        ((uint4*)dst)[i] = u;
    }
}

// ================= cp.async 5-stage TF32 GEMM, 128x128 block, 2 CTAs/SM =================
// Block 128x128, BK=16, 4 warps (2x2), warp tile 64x64.
// A stage [128][20] fp32 (pad 4), B stage [16][136] fp32 (pad 8) — conflict-free frags.
#define PG_STAGES 5
#define PG_ASTAGE (128*20)
#define PG_BSTAGE (16*136)
#define PG_BBASE  (PG_STAGES*PG_ASTAGE*4)
#define PG_SMEM   (PG_STAGES*(PG_ASTAGE+PG_BSTAGE)*4)

__device__ __forceinline__ void cp16(uint32_t dst, const float* src, int sz) {
    asm volatile("cp.async.cg.shared.global [%0], [%1], 16, %2;"
                 :: "r"(dst), "l"(src), "r"(sz) : "memory");
}

template<int ACT>
__global__ void __launch_bounds__(128, 2)
pgemm_kernel(const float* __restrict__ A, const float* __restrict__ Bm,
             const float* __restrict__ bias, float* __restrict__ C,
             int M, int N, int K)
{
    extern __shared__ char dsm[];
    float* Asm = (float*)dsm;
    float* Bsm = (float*)(dsm + PG_BBASE);
    const uint32_t sbase = (uint32_t)__cvta_generic_to_shared(dsm);

    const int tid  = threadIdx.x;
    const int bm   = blockIdx.y * 128;
    const int bn   = blockIdx.x * 128;
    const int wid  = tid >> 5;
    const int lane = tid & 31;
    const int wm   = (wid & 1) * 64;
    const int wn   = (wid >> 1) * 64;
    const int g    = lane >> 2;
    const int tig  = lane & 3;

    float acc[4][8][4];
#pragma unroll
    for (int i = 0; i < 4; i++)
#pragma unroll
        for (int j = 0; j < 8; j++)
#pragma unroll
            for (int c = 0; c < 4; c++) acc[i][j][c] = 0.f;

    // producers: A: thread -> row tid (16 floats); B: thread -> row tid>>3, cols (tid&7)*16
    const int arow = tid;
    const bool aval = (bm + arow) < M;
    const float* Asrc = A + (size_t)(aval ? (bm + arow) : 0) * K;
    const uint32_t adst = sbase + (arow * 20) * 4;
    const int asz = aval ? 16 : 0;

    const int brow = tid >> 3;
    const int bc   = (tid & 7) * 16;
    const float* Bsrc = Bm + (size_t)brow * N + bn + bc;
    const uint32_t bdst = sbase + PG_BBASE + (brow * 136 + bc) * 4;

    const int nk = K / 16;

#define PG_ISSUE(kt, s)                                                        \
    {                                                                          \
        const float* as_ = Asrc + (kt) * 16;                                   \
        uint32_t ad_ = adst + (s) * (PG_ASTAGE * 4);                           \
        cp16(ad_, as_, asz);      cp16(ad_ + 16, as_ + 4, asz);                \
        cp16(ad_ + 32, as_ + 8, asz); cp16(ad_ + 48, as_ + 12, asz);           \
        const float* bs_ = Bsrc + (size_t)(kt) * 16 * N;                       \
        uint32_t bd_ = bdst + (s) * (PG_BSTAGE * 4);                           \
        cp16(bd_,      bs_,      16); cp16(bd_ + 16, bs_ + 4,  16);            \
        cp16(bd_ + 32, bs_ + 8,  16); cp16(bd_ + 48, bs_ + 12, 16);            \
    }

#pragma unroll
    for (int s = 0; s < PG_STAGES - 1; s++) {
        PG_ISSUE(s, s);
        asm volatile("cp.async.commit_group;" ::: "memory");
    }

    for (int kt = 0; kt < nk; kt++) {
        const int buf = kt % PG_STAGES;
        asm volatile("cp.async.wait_group %0;" :: "n"(PG_STAGES - 2) : "memory");
        __syncthreads();

        const int nt = kt + PG_STAGES - 1;
        if (nt < nk) { PG_ISSUE(nt, nt % PG_STAGES); }
        asm volatile("cp.async.commit_group;" ::: "memory");

        const float* Ab = Asm + buf * PG_ASTAGE;
        const float* Bb = Bsm + buf * PG_BSTAGE;
#pragma unroll
        for (int kk = 0; kk < 2; kk++) {
            const float* br0 = Bb + (kk * 8 + tig) * 136;
            const float* br1 = Bb + (kk * 8 + tig + 4) * 136;
            uint32_t bf0[8], bf1[8];
#pragma unroll
            for (int j = 0; j < 8; j++) {
                const int n0 = wn + j * 8 + g;
                bf0[j] = __float_as_uint(br0[n0]);
                bf1[j] = __float_as_uint(br1[n0]);
            }
#pragma unroll
            for (int i = 0; i < 4; i++) {
                const float* ar = Ab + (wm + i * 16 + g) * 20 + kk * 8 + tig;
                uint32_t a0 = __float_as_uint(ar[0]);
                uint32_t a1 = __float_as_uint(ar[160]);
                uint32_t a2 = __float_as_uint(ar[4]);
                uint32_t a3 = __float_as_uint(ar[164]);
#pragma unroll
                for (int j = 0; j < 8; j++) {
                    asm volatile(
                        "mma.sync.aligned.m16n8k8.row.col.f32.tf32.tf32.f32 "
                        "{%0,%1,%2,%3}, {%4,%5,%6,%7}, {%8,%9}, {%0,%1,%2,%3};"
                        : "+f"(acc[i][j][0]), "+f"(acc[i][j][1]),
                          "+f"(acc[i][j][2]), "+f"(acc[i][j][3])
                        : "r"(a0), "r"(a1), "r"(a2), "r"(a3),
                          "r"(bf0[j]), "r"(bf1[j]));
                }
            }
        }
    }

#pragma unroll
    for (int i = 0; i < 4; i++) {
        const int r0 = bm + wm + i * 16 + g;
        const int r1 = r0 + 8;
#pragma unroll
        for (int j = 0; j < 8; j++) {
            const int col = bn + wn + j * 8 + 2 * tig;
            const float bv0 = bias[col];
            const float bv1 = bias[col + 1];
            float v0a = acc[i][j][0] + bv0;
            float v1a = acc[i][j][1] + bv1;
            float v2a = acc[i][j][2] + bv0;
            float v3a = acc[i][j][3] + bv1;
            if (ACT == 1) { v0a = gelu_f(v0a); v1a = gelu_f(v1a); v2a = gelu_f(v2a); v3a = gelu_f(v3a); }
            if (r0 < M) *(float2*)&C[(size_t)r0 * N + col] = make_float2(v0a, v1a);
            if (r1 < M) *(float2*)&C[(size_t)r1 * N + col] = make_float2(v2a, v3a);
        }
    }
}

// ---------------- RNA register-staged TF32 GEMM (conv only) ----------------
template<int ACT>
__global__ void __launch_bounds__(256, 1)
tgemm_kernel(const float* __restrict__ A, const float* __restrict__ Bm,
             const float* __restrict__ bias, float* __restrict__ C,
             int M, int N, int K)
{
    extern __shared__ char dsm[];
    uint32_t (*As)[2048]    = (uint32_t (*)[2048])dsm;
    uint32_t (*Bs)[16][264] = (uint32_t (*)[16][264])(dsm + 16384);

    const int tid  = threadIdx.x;
    const int bm   = blockIdx.y * 128;
    const int bn   = blockIdx.x * 256;
    const int wid  = tid >> 5;
    const int lane = tid & 31;
    const int wm   = (wid & 1) * 64;
    const int wn   = (wid >> 1) * 64;
    const int g    = lane >> 2;
    const int tig  = lane & 3;

    float acc[4][8][4];
#pragma unroll
    for (int i = 0; i < 4; i++)
#pragma unroll
        for (int j = 0; j < 8; j++)
#pragma unroll
            for (int c = 0; c < 4; c++) acc[i][j][c] = 0.f;

    const int p   = tid & 31;
    const int mb  = (tid >> 5) & 7;
    const int gA  = p >> 2;
    const int tA  = p & 3;
    const int mlo = mb * 16 + gA;
    const int mhi = mlo + 8;
    const bool v0 = (bm + mlo) < M;
    const bool v1 = (bm + mhi) < M;
    const float* Alo = A + (size_t)(v0 ? (bm + mlo) : 0) * K;
    const float* Ahi = A + (size_t)(v1 ? (bm + mhi) : 0) * K;
    const int aoff0 = ((0 * 8 + mb) * 32 + p) * 4;
    const int aoff1 = ((1 * 8 + mb) * 32 + p) * 4;

    const int br  = tid >> 6;
    const int bc4 = (tid & 63) << 2;
    const float* Bbase = Bm + bn + bc4;

    const int nk = K / 16;

    {
#pragma unroll
        for (int kk = 0; kk < 2; kk++) {
            const int kl = kk * 8 + tA;
            float x00 = v0 ? Alo[kl]     : 0.f;
            float x01 = v0 ? Alo[kl + 4] : 0.f;
            float x10 = v1 ? Ahi[kl]     : 0.f;
            float x11 = v1 ? Ahi[kl + 4] : 0.f;
            uint32_t* dst = &As[0][kk ? aoff1 : aoff0];
            dst[0] = f2tf(x00); dst[1] = f2tf(x10);
            dst[2] = f2tf(x01); dst[3] = f2tf(x11);
        }
#pragma unroll
        for (int m = 0; m < 4; m++) {
            const int row = br + 4 * m;
            float4 b = *(const float4*)(Bbase + (size_t)row * N);
            *(uint4*)&Bs[0][row][bc4] = make_uint4(f2tf(b.x), f2tf(b.y), f2tf(b.z), f2tf(b.w));
        }
    }
    __syncthreads();

    for (int kt = 0; kt < nk; kt++) {
        const int cur = kt & 1;
        const bool have_next = (kt + 1 < nk);

        float na[2][4];
        float4 nb[4];
        if (have_next) {
            const int off = (kt + 1) * 16;
#pragma unroll
            for (int kk = 0; kk < 2; kk++) {
                const int kl = off + kk * 8 + tA;
                na[kk][0] = v0 ? Alo[kl]     : 0.f;
                na[kk][1] = v1 ? Ahi[kl]     : 0.f;
                na[kk][2] = v0 ? Alo[kl + 4] : 0.f;
                na[kk][3] = v1 ? Ahi[kl + 4] : 0.f;
            }
#pragma unroll
            for (int m = 0; m < 4; m++)
                nb[m] = *(const float4*)(Bbase + (size_t)(off + br + 4 * m) * N);
        }

#pragma unroll
        for (int kk = 0; kk < 2; kk++) {
            const uint32_t* brow0 = &Bs[cur][kk * 8 + tig][0];
            const uint32_t* brow1 = &Bs[cur][kk * 8 + tig + 4][0];
            uint32_t bf0[8], bf1[8];
#pragma unroll
            for (int j = 0; j < 8; j++) {
                const int n0 = wn + j * 8 + g;
                bf0[j] = brow0[n0];
                bf1[j] = brow1[n0];
            }
#pragma unroll
            for (int i = 0; i < 4; i++) {
                const int mbi = (wm >> 4) + i;
                uint4 af = *(const uint4*)&As[cur][((kk * 8 + mbi) * 32 + lane) * 4];
#pragma unroll
                for (int j = 0; j < 8; j++) {
                    asm volatile(
                        "mma.sync.aligned.m16n8k8.row.col.f32.tf32.tf32.f32 "
                        "{%0,%1,%2,%3}, {%4,%5,%6,%7}, {%8,%9}, {%0,%1,%2,%3};"
                        : "+f"(acc[i][j][0]), "+f"(acc[i][j][1]),
                          "+f"(acc[i][j][2]), "+f"(acc[i][j][3])
                        : "r"(af.x), "r"(af.y), "r"(af.z), "r"(af.w),
                          "r"(bf0[j]), "r"(bf1[j]));
                }
            }
        }

        if (have_next) {
            const int nxt = cur ^ 1;
#pragma unroll
            for (int kk = 0; kk < 2; kk++) {
                uint32_t* dst = &As[nxt][kk ? aoff1 : aoff0];
                dst[0] = f2tf(na[kk][0]); dst[1] = f2tf(na[kk][1]);
                dst[2] = f2tf(na[kk][2]); dst[3] = f2tf(na[kk][3]);
            }
#pragma unroll
            for (int m = 0; m < 4; m++) {
                const int row = br + 4 * m;
                *(uint4*)&Bs[nxt][row][bc4] =
                    make_uint4(f2tf(nb[m].x), f2tf(nb[m].y), f2tf(nb[m].z), f2tf(nb[m].w));
            }
        }
        __syncthreads();
    }

#pragma unroll
    for (int i = 0; i < 4; i++) {
        const int r0 = bm + wm + i * 16 + g;
        const int r1 = r0 + 8;
#pragma unroll
        for (int j = 0; j < 8; j++) {
            const int col = bn + wn + j * 8 + 2 * tig;
            const float bv0 = bias[col];
            const float bv1 = bias[col + 1];
            float v0a = acc[i][j][0] + bv0;
            float v1a = acc[i][j][1] + bv1;
            float v2a = acc[i][j][2] + bv0;
            float v3a = acc[i][j][3] + bv1;
            if (ACT == 1) { v0a = gelu_f(v0a); v1a = gelu_f(v1a); v2a = gelu_f(v2a); v3a = gelu_f(v3a); }
            if (r0 < M) *(float2*)&C[(size_t)r0 * N + col] = make_float2(v0a, v1a);
            if (r1 < M) *(float2*)&C[(size_t)r1 * N + col] = make_float2(v2a, v3a);
        }
    }
}

#define GEMM_SMEM (16384 + 2*16*264*4)

// ---------------- assemble h ----------------
__global__ void assemble_kernel(const float* __restrict__ x,
                                const float* __restrict__ rnd,
                                const int*   __restrict__ perm,
                                const float* __restrict__ mask_tok,
                                const float* __restrict__ agg_tok,
                                const float* __restrict__ pos_emb,
                                float* __restrict__ h,
                                float* __restrict__ mask_pos)
{
    int row = blockIdx.x;
    int b   = row / SEQ;
    int sp  = row - b * SEQ;
    int tid = threadIdx.x;
    float* hp = h + (size_t)row * D_;

    if (sp == 0) {
        hp[tid]       = agg_tok[tid];
        hp[tid + 256] = agg_tok[tid + 256];
        hp[tid + 512] = agg_tok[tid + 512];
        return;
    }
    int s = sp - 1;
    int i = b * S_ + s;
    float r0 = rnd[i * 3 + 0];
    float r1 = rnd[i * 3 + 1];
    float r2 = rnd[i * 3 + 2];
    bool  sel = (r0 <= 0.2f);
    float m  = (sel && r1 <= 0.8f) ? 1.f : 0.f;
    float rd = (sel && r1 > 0.8f && r2 <= 0.5f) ? 1.f : 0.f;
    if (tid == 0) mask_pos[i] = sel ? 1.f : 0.f;

    int pi = perm[i];
    const float* xp = x + (size_t)i  * D_;
    const float* sh = x + (size_t)pi * D_;
    const float* pe = pos_emb + (size_t)s * D_;
    float keep = 1.f - m - rd;

#pragma unroll
    for (int e = 0; e < 3; e++) {
        int d = tid + e * 256;
        hp[d] = xp[d] * keep + mask_tok[d] * m + sh[d] * rd + pe[d];
    }
}

// ---------------- attention ----------------
__global__ void __launch_bounds__(256)
attn_kernel(const float* __restrict__ Q, const float* __restrict__ K,
            const float* __restrict__ V, float* __restrict__ O)
{
    extern __shared__ float sm[];
    float* Kt    = sm;
    float* Vs    = Kt + 64 * 257;
    float* probs = Vs + 257 * 64;
    float* qbuf  = probs + 8 * 257;

    int hh = blockIdx.x;
    int bb = blockIdx.y;
    int tid = threadIdx.x;
    const size_t base = ((size_t)bb * SEQ) * D_ + (size_t)hh * DKH;

    for (int idx = tid; idx < SEQ * DKH; idx += 256) {
        int k = idx >> 6;
        int d = idx & 63;
        float kv = K[base + (size_t)k * D_ + d];
        Kt[d * SEQ + k] = kv;
        Vs[idx] = V[base + (size_t)k * D_ + d];
    }
    __syncthreads();

    int w = tid >> 5, lane = tid & 31;
    float* qw = qbuf + w * 64;
    float* pw = probs + w * SEQ;

    for (int q = w; q < SEQ; q += 8) {
        const float* qp = Q + base + (size_t)q * D_;
        qw[lane]      = qp[lane];
        qw[lane + 32] = qp[lane + 32];
        __syncwarp();

        float s[9];
#pragma unroll
        for (int j = 0; j < 9; j++) s[j] = 0.f;

#pragma unroll 4
        for (int d = 0; d < 64; d++) {
            float qv = qw[d];
            const float* kr = &Kt[d * SEQ + lane];
#pragma unroll
            for (int j = 0; j < 9; j++)
                s[j] += qv * kr[j * 32];
        }

        float mx = -1e30f;
#pragma unroll
        for (int j = 0; j < 9; j++) {
            int k = lane + j * 32;
            s[j] = (k < SEQ) ? s[j] * 0.125f : -1e30f;
            mx = fmaxf(mx, s[j]);
        }
        for (int off = 16; off; off >>= 1)
            mx = fmaxf(mx, __shfl_xor_sync(0xffffffffu, mx, off));

        float sum = 0.f;
#pragma unroll
        for (int j = 0; j < 9; j++) {
            float e = __expf(s[j] - mx);
            sum += e;
            s[j] = e;
        }
        for (int off = 16; off; off >>= 1)
            sum += __shfl_xor_sync(0xffffffffu, sum, off);
        float inv = 1.f / sum;
#pragma unroll
        for (int j = 0; j < 9; j++) {
            int k = lane + j * 32;
            if (k < SEQ) pw[k] = s[j] * inv;
        }
        __syncwarp();

        float o0 = 0.f, o1 = 0.f;
#pragma unroll 4
        for (int k = 0; k < SEQ; k++) {
            float pv = pw[k];
            float2 v2 = *(const float2*)&Vs[k * 64 + 2 * lane];
            o0 += pv * v2.x;
            o1 += pv * v2.y;
        }
        *(float2*)&O[base + (size_t)q * D_ + 2 * lane] = make_float2(o0, o1);
        __syncwarp();
    }
}

// ---------------- residual + LayerNorm (OUT=0: to h; OUT=1: scatter to agg/pred) ----------------
template<int OUT>
__global__ void add_ln_kernel(const float* __restrict__ H, const float* __restrict__ Dl,
                              const float* __restrict__ g, const float* __restrict__ be,
                              float* __restrict__ Out, float* __restrict__ Pred)
{
    int row = blockIdx.x, tid = threadIdx.x;
    const float* hp = H  + (size_t)row * D_;
    const float* dp = Dl + (size_t)row * D_;
    float v0 = hp[tid]       + dp[tid];
    float v1 = hp[tid + 256] + dp[tid + 256];
    float v2 = hp[tid + 512] + dp[tid + 512];

    __shared__ float red[8];
    __shared__ float s_mu, s_var;
    int lane = tid & 31, w = tid >> 5;

    float s = v0 + v1 + v2;
    for (int off = 16; off; off >>= 1) s += __shfl_xor_sync(0xffffffffu, s, off);
    if (lane == 0) red[w] = s;
    __syncthreads();
    if (tid == 0) {
        float t = 0.f;
        for (int i = 0; i < 8; i++) t += red[i];
        s_mu = t * (1.0f / 768.0f);
    }
    __syncthreads();
    float mu = s_mu;
    float d0 = v0 - mu, d1 = v1 - mu, d2 = v2 - mu;
    float qv = d0 * d0 + d1 * d1 + d2 * d2;
    for (int off = 16; off; off >>= 1) qv += __shfl_xor_sync(0xffffffffu, qv, off);
    if (lane == 0) red[w] = qv;
    __syncthreads();
    if (tid == 0) {
        float t = 0.f;
        for (int i = 0; i < 8; i++) t += red[i];
        s_var = t * (1.0f / 768.0f);
    }
    __syncthreads();
    float rs = rsqrtf(s_var + 1e-6f);

    float* op;
    if (OUT == 0) {
        op = Out + (size_t)row * D_;
    } else {
        int b  = row / SEQ;
        int sp = row - b * SEQ;
        if (sp == 0) op = Out + (size_t)b * D_;                          // aggregated
        else         op = Pred + (size_t)(b * S_ + sp - 1) * D_;         // predictions
    }
    op[tid]       = d0 * rs * g[tid]       + be[tid];
    op[tid + 256] = d1 * rs * g[tid + 256] + be[tid + 256];
    op[tid + 512] = d2 * rs * g[tid + 512] + be[tid + 512];
}

// ---------------- host ----------------
static inline void run_pgemm(const float* A, const float* Bw, const float* bias,
                             float* C, int M, int N, int K, bool gelu)
{
    dim3 grid(N / 128, (M + 127) / 128);
    if (gelu) pgemm_kernel<1><<<grid, 128, PG_SMEM>>>(A, Bw, bias, C, M, N, K);
    else      pgemm_kernel<0><<<grid, 128, PG_SMEM>>>(A, Bw, bias, C, M, N, K);
}

extern "C" void kernel_launch(void* const* d_in, const int* in_sizes, int n_in,
                              void* d_out, int out_size)
{
    const float* inputs     = (const float*)d_in[0];
    const float* randomness = (const float*)d_in[1];
    const int*   perm       = (const int*)  d_in[2];
    const float* conv_w     = (const float*)d_in[3];
    const float* conv_b     = (const float*)d_in[4];
    const float* pos_emb    = (const float*)d_in[5];
    const float* mask_tok   = (const float*)d_in[6];
    const float* agg_tok    = (const float*)d_in[7];
    const float* wq  = (const float*)d_in[8];
    const float* bq  = (const float*)d_in[9];
    const float* wk  = (const float*)d_in[10];
    const float* bk  = (const float*)d_in[11];
    const float* wv  = (const float*)d_in[12];
    const float* bv  = (const float*)d_in[13];
    const float* wo  = (const float*)d_in[14];
    const float* bo  = (const float*)d_in[15];
    const float* ln1g = (const float*)d_in[16];
    const float* ln1b = (const float*)d_in[17];
    const float* w1  = (const float*)d_in[18];
    const float* b1  = (const float*)d_in[19];
    const float* w2  = (const float*)d_in[20];
    const float* b2  = (const float*)d_in[21];
    const float* ln2g = (const float*)d_in[22];
    const float* ln2b = (const float*)d_in[23];

    float* out      = (float*)d_out;
    float* out_agg  = out;
    float* out_pred = out + 49152;
    float* out_mask = out + 12632064;
    float* out_emb  = out + 12648448;

    float *h, *q, *k, *v, *o, *t, *f, *wr;
    cudaGetSymbolAddress((void**)&h, g_h);
    cudaGetSymbolAddress((void**)&q, g_q);
    cudaGetSymbolAddress((void**)&k, g_k);
    cudaGetSymbolAddress((void**)&v, g_v);
    cudaGetSymbolAddress((void**)&o, g_o);
    cudaGetSymbolAddress((void**)&t, g_t);
    cudaGetSymbolAddress((void**)&f, g_f);
    cudaGetSymbolAddress((void**)&wr, g_wr);

    cudaFuncSetAttribute(tgemm_kernel<0>, cudaFuncAttributeMaxDynamicSharedMemorySize, GEMM_SMEM);
    cudaFuncSetAttribute(pgemm_kernel<0>, cudaFuncAttributeMaxDynamicSharedMemorySize, PG_SMEM);
    cudaFuncSetAttribute(pgemm_kernel<1>, cudaFuncAttributeMaxDynamicSharedMemorySize, PG_SMEM);

    // pre-round weights to tf32 RNA
    rnd_kernel<<<1152, 256>>>(wq, wr + RQ_OFF, 294912);
    rnd_kernel<<<1152, 256>>>(wk, wr + RK_OFF, 294912);
    rnd_kernel<<<1152, 256>>>(wv, wr + RV_OFF, 294912);
    rnd_kernel<<<1152, 256>>>(wo, wr + RO_OFF, 294912);
    rnd_kernel<<<4608, 256>>>(w1, wr + R1_OFF, 1179648);
    rnd_kernel<<<4608, 256>>>(w2, wr + R2_OFF, 1179648);

    // conv (stride == kernel => pure GEMM), RNA path, writes embeddings directly
    {
        dim3 grid(D_ / 256, (BSR + 127) / 128);
        tgemm_kernel<0><<<grid, 256, GEMM_SMEM>>>(inputs, conv_w, conv_b, out_emb, BSR, D_, 512);
    }

    assemble_kernel<<<ROWS, 256>>>(out_emb, randomness, perm, mask_tok, agg_tok,
                                   pos_emb, h, out_mask);

    const int SMEM_ATTN = (64 * SEQ + SEQ * 64 + 8 * SEQ + 8 * 64) * (int)sizeof(float);
    cudaFuncSetAttribute(attn_kernel, cudaFuncAttributeMaxDynamicSharedMemorySize, SMEM_ATTN);

    for (int l = 0; l < 2; l++) {
        const float* wq_r = wr + RQ_OFF + (size_t)l * 589824;
        const float* wk_r = wr + RK_OFF + (size_t)l * 589824;
        const float* wv_r = wr + RV_OFF + (size_t)l * 589824;
        const float* wo_r = wr + RO_OFF + (size_t)l * 589824;
        const float* w1_r = wr + R1_OFF + (size_t)l * 2359296;
        const float* w2_r = wr + R2_OFF + (size_t)l * 2359296;

        run_pgemm(h, wq_r, bq + l * D_, q, ROWS, D_, D_, false);
        run_pgemm(h, wk_r, bk + l * D_, k, ROWS, D_, D_, false);
        run_pgemm(h, wv_r, bv + l * D_, v, ROWS, D_, D_, false);

        attn_kernel<<<dim3(HEADS, B_), 256, SMEM_ATTN>>>(q, k, v, o);

        run_pgemm(o, wo_r, bo + l * D_, t, ROWS, D_, D_, false);
        add_ln_kernel<0><<<ROWS, 256>>>(h, t, ln1g + l * D_, ln1b + l * D_, h, nullptr);

        run_pgemm(h, w1_r, b1 + l * F_, f, ROWS, F_, D_, true);
        run_pgemm(f, w2_r, b2 + l * D_, t, ROWS, D_, F_, false);
        if (l == 0)
            add_ln_kernel<0><<<ROWS, 256>>>(h, t, ln2g + l * D_, ln2b + l * D_, h, nullptr);
        else
            add_ln_kernel<1><<<ROWS, 256>>>(h, t, ln2g + l * D_, ln2b + l * D_, out_agg, out_pred);
    }
}

// round 8
// speedup vs baseline: 1.4740x; 1.4740x over previous
#include <cuda_runtime.h>
#include <cuda_fp16.h>
#include <math.h>
#include <stdint.h>

#define B_    64
#define SEQ   257
#define S_    256
#define D_    768
#define F_    3072
#define HEADS 12
#define DKH   64
#define ROWS  (B_*SEQ)     // 16448
#define BSR   (B_*S_)      // 16384

// ---------------- scratch ----------------
__device__ float  g_h [(size_t)ROWS*D_];
__device__ float  g_q [(size_t)ROWS*D_];
__device__ float  g_k [(size_t)ROWS*D_];
__device__ float  g_v [(size_t)ROWS*D_];
__device__ float  g_t [(size_t)ROWS*D_];
__device__ __half g_h16[(size_t)ROWS*D_];
__device__ __half g_o16[(size_t)ROWS*D_];
__device__ __half g_f16[(size_t)ROWS*F_];
__device__ __half g_in16[(size_t)BSR*512];
__device__ __half g_wt[14548992];        // fp16 transposed weights [N][K]

// half offsets in g_wt
#define CW_OFF 0
#define WQ_OFF 393216
#define WK_OFF 1572864
#define WV_OFF 2752512
#define WO_OFF 3932160
#define W1_OFF 5111808
#define W2_OFF 9830400

__device__ __forceinline__ float gelu_f(float x) {
    float x3 = x * x * x;
    float t = tanhf(0.7978845608028654f * (x + 0.044715f * x3));
    return 0.5f * x * (1.0f + t);
}

// ---------------- prep: convert inputs fp32->fp16 ----------------
__global__ void in16_kernel(const float* __restrict__ src, __half* __restrict__ dst, int n4)
{
    int i = blockIdx.x * 256 + threadIdx.x;
    if (i < n4) {
        float4 v = ((const float4*)src)[i];
        ((half2*)dst)[2 * i]     = __floats2half2_rn(v.x, v.y);
        ((half2*)dst)[2 * i + 1] = __floats2half2_rn(v.z, v.w);
    }
}

// ---------------- prep: transpose+convert weights [K][N] fp32 -> [N][K] fp16 ----------------
__global__ void wt16_kernel(const float* __restrict__ src, __half* __restrict__ dst, int K, int N)
{
    __shared__ float tile[32][33];
    int k0 = blockIdx.y * 32, n0 = blockIdx.x * 32;
    int tx = threadIdx.x, ty = threadIdx.y;     // 32 x 8
#pragma unroll
    for (int i = 0; i < 4; i++)
        tile[ty + i * 8][tx] = src[(size_t)(k0 + ty + i * 8) * N + n0 + tx];
    __syncthreads();
#pragma unroll
    for (int i = 0; i < 4; i++)
        dst[(size_t)(n0 + ty + i * 8) * K + k0 + tx] = __float2half(tile[tx][ty + i * 8]);
}

// ================= cp.async 5-stage FP16 GEMM =================
// C = A(MxK fp16) @ Bt(NxK fp16)^T + bias (+GELU). Block 128x256, BK=32,
// 256 threads (8 warps 2x4), warp 64x64, mma.m16n8k16.f16, fp32 accum.
// smem rows padded to 80B (20 words): all fragment LDS.32 are 32-bank conflict-free.
#define PG_STAGES   5
#define PG_ASTAGE_B (128*80)
#define PG_BSTAGE_B (256*80)
#define PG_BBASE    (PG_STAGES*PG_ASTAGE_B)
#define PG_SMEM     (PG_STAGES*(PG_ASTAGE_B+PG_BSTAGE_B))

__device__ __forceinline__ void cp16h(uint32_t dst, const __half* src, int sz) {
    asm volatile("cp.async.cg.shared.global [%0], [%1], 16, %2;"
                 :: "r"(dst), "l"(src), "r"(sz) : "memory");
}

template<int ACT, int OUTHALF>
__global__ void __launch_bounds__(256, 1)
hgemm_kernel(const __half* __restrict__ A, const __half* __restrict__ Bt,
             const float* __restrict__ bias, float* __restrict__ C,
             __half* __restrict__ C16, int M, int N, int K)
{
    extern __shared__ char dsm[];
    const uint32_t sbase = (uint32_t)__cvta_generic_to_shared(dsm);

    const int tid  = threadIdx.x;
    const int bm   = blockIdx.y * 128;
    const int bn   = blockIdx.x * 256;
    const int wid  = tid >> 5;
    const int lane = tid & 31;
    const int wm   = (wid & 1) * 64;
    const int wn   = (wid >> 1) * 64;
    const int g    = lane >> 2;
    const int tig  = lane & 3;

    float acc[4][8][4];
#pragma unroll
    for (int i = 0; i < 4; i++)
#pragma unroll
        for (int j = 0; j < 8; j++)
#pragma unroll
            for (int c = 0; c < 4; c++) acc[i][j][c] = 0.f;

    // producers: A: thread -> row tid>>1, 32B chunk tid&1. B: thread -> n-row tid, 64B.
    const int arow = tid >> 1;
    const bool aval = (bm + arow) < M;
    const __half* Asrc = A + (size_t)(aval ? (bm + arow) : 0) * K + (tid & 1) * 16;
    const uint32_t adst = sbase + arow * 80 + (tid & 1) * 32;
    const int asz = aval ? 16 : 0;

    const __half* Bsrc = Bt + (size_t)(bn + tid) * K;
    const uint32_t bdst = sbase + PG_BBASE + tid * 80;

    const int nk = K / 32;

#define PG_ISSUE(kt, s)                                                         \
    {                                                                           \
        const __half* as_ = Asrc + (kt) * 32;                                   \
        uint32_t ad_ = adst + (s) * PG_ASTAGE_B;                                \
        cp16h(ad_, as_, asz); cp16h(ad_ + 16, as_ + 8, asz);                    \
        const __half* bs_ = Bsrc + (kt) * 32;                                   \
        uint32_t bd_ = bdst + (s) * PG_BSTAGE_B;                                \
        cp16h(bd_,      bs_,      16); cp16h(bd_ + 16, bs_ + 8,  16);           \
        cp16h(bd_ + 32, bs_ + 16, 16); cp16h(bd_ + 48, bs_ + 24, 16);           \
    }

#pragma unroll
    for (int s = 0; s < PG_STAGES - 1; s++) {
        PG_ISSUE(s, s);
        asm volatile("cp.async.commit_group;" ::: "memory");
    }

    for (int kt = 0; kt < nk; kt++) {
        const int buf = kt % PG_STAGES;
        asm volatile("cp.async.wait_group %0;" :: "n"(PG_STAGES - 2) : "memory");
        __syncthreads();

        const int nt = kt + PG_STAGES - 1;
        if (nt < nk) { PG_ISSUE(nt, nt % PG_STAGES); }
        asm volatile("cp.async.commit_group;" ::: "memory");

        const uint32_t* Aw = (const uint32_t*)(dsm + buf * PG_ASTAGE_B);
        const uint32_t* Bw = (const uint32_t*)(dsm + PG_BBASE + buf * PG_BSTAGE_B);
#pragma unroll
        for (int kk = 0; kk < 2; kk++) {
            const int kw = kk * 8 + tig;
            uint32_t bf0[8], bf1[8];
#pragma unroll
            for (int j = 0; j < 8; j++) {
                const int n0 = wn + j * 8 + g;
                bf0[j] = Bw[n0 * 20 + kw];
                bf1[j] = Bw[n0 * 20 + kw + 4];
            }
#pragma unroll
            for (int i = 0; i < 4; i++) {
                const int r = wm + i * 16 + g;
                uint32_t a0 = Aw[r * 20 + kw];
                uint32_t a1 = Aw[(r + 8) * 20 + kw];
                uint32_t a2 = Aw[r * 20 + kw + 4];
                uint32_t a3 = Aw[(r + 8) * 20 + kw + 4];
#pragma unroll
                for (int j = 0; j < 8; j++) {
                    asm volatile(
                        "mma.sync.aligned.m16n8k16.row.col.f32.f16.f16.f32 "
                        "{%0,%1,%2,%3}, {%4,%5,%6,%7}, {%8,%9}, {%0,%1,%2,%3};"
                        : "+f"(acc[i][j][0]), "+f"(acc[i][j][1]),
                          "+f"(acc[i][j][2]), "+f"(acc[i][j][3])
                        : "r"(a0), "r"(a1), "r"(a2), "r"(a3),
                          "r"(bf0[j]), "r"(bf1[j]));
                }
            }
        }
    }

#pragma unroll
    for (int i = 0; i < 4; i++) {
        const int r0 = bm + wm + i * 16 + g;
        const int r1 = r0 + 8;
#pragma unroll
        for (int j = 0; j < 8; j++) {
            const int col = bn + wn + j * 8 + 2 * tig;
            const float bv0 = bias[col];
            const float bv1 = bias[col + 1];
            float v0a = acc[i][j][0] + bv0;
            float v1a = acc[i][j][1] + bv1;
            float v2a = acc[i][j][2] + bv0;
            float v3a = acc[i][j][3] + bv1;
            if (ACT == 1) { v0a = gelu_f(v0a); v1a = gelu_f(v1a); v2a = gelu_f(v2a); v3a = gelu_f(v3a); }
            if (OUTHALF) {
                if (r0 < M) *(half2*)&C16[(size_t)r0 * N + col] = __floats2half2_rn(v0a, v1a);
                if (r1 < M) *(half2*)&C16[(size_t)r1 * N + col] = __floats2half2_rn(v2a, v3a);
            } else {
                if (r0 < M) *(float2*)&C[(size_t)r0 * N + col] = make_float2(v0a, v1a);
                if (r1 < M) *(float2*)&C[(size_t)r1 * N + col] = make_float2(v2a, v3a);
            }
        }
    }
}

// ---------------- assemble h (+fp16 copy) ----------------
__global__ void assemble_kernel(const float* __restrict__ x,
                                const float* __restrict__ rnd,
                                const int*   __restrict__ perm,
                                const float* __restrict__ mask_tok,
                                const float* __restrict__ agg_tok,
                                const float* __restrict__ pos_emb,
                                float* __restrict__ h, __half* __restrict__ h16,
                                float* __restrict__ mask_pos)
{
    int row = blockIdx.x;
    int b   = row / SEQ;
    int sp  = row - b * SEQ;
    int tid = threadIdx.x;
    float*  hp  = h   + (size_t)row * D_;
    __half* hp16 = h16 + (size_t)row * D_;

    if (sp == 0) {
#pragma unroll
        for (int e = 0; e < 3; e++) {
            int d = tid + e * 256;
            float v = agg_tok[d];
            hp[d] = v; hp16[d] = __float2half(v);
        }
        return;
    }
    int s = sp - 1;
    int i = b * S_ + s;
    float r0 = rnd[i * 3 + 0];
    float r1 = rnd[i * 3 + 1];
    float r2 = rnd[i * 3 + 2];
    bool  sel = (r0 <= 0.2f);
    float m  = (sel && r1 <= 0.8f) ? 1.f : 0.f;
    float rd = (sel && r1 > 0.8f && r2 <= 0.5f) ? 1.f : 0.f;
    if (tid == 0) mask_pos[i] = sel ? 1.f : 0.f;

    int pi = perm[i];
    const float* xp = x + (size_t)i  * D_;
    const float* sh = x + (size_t)pi * D_;
    const float* pe = pos_emb + (size_t)s * D_;
    float keep = 1.f - m - rd;

#pragma unroll
    for (int e = 0; e < 3; e++) {
        int d = tid + e * 256;
        float v = xp[d] * keep + mask_tok[d] * m + sh[d] * rd + pe[d];
        hp[d] = v; hp16[d] = __float2half(v);
    }
}

// ---------------- attention (fp32 math, fp16 output) ----------------
__global__ void __launch_bounds__(256)
attn_kernel(const float* __restrict__ Q, const float* __restrict__ K,
            const float* __restrict__ V, __half* __restrict__ O16)
{
    extern __shared__ float sm[];
    float* Kt    = sm;
    float* Vs    = Kt + 64 * 257;
    float* probs = Vs + 257 * 64;
    float* qbuf  = probs + 8 * 257;

    int hh = blockIdx.x;
    int bb = blockIdx.y;
    int tid = threadIdx.x;
    const size_t base = ((size_t)bb * SEQ) * D_ + (size_t)hh * DKH;

    for (int idx = tid; idx < SEQ * DKH; idx += 256) {
        int k = idx >> 6;
        int d = idx & 63;
        Kt[d * SEQ + k] = K[base + (size_t)k * D_ + d];
        Vs[idx] = V[base + (size_t)k * D_ + d];
    }
    __syncthreads();

    int w = tid >> 5, lane = tid & 31;
    float* qw = qbuf + w * 64;
    float* pw = probs + w * SEQ;

    for (int q = w; q < SEQ; q += 8) {
        const float* qp = Q + base + (size_t)q * D_;
        qw[lane]      = qp[lane];
        qw[lane + 32] = qp[lane + 32];
        __syncwarp();

        float s[9];
#pragma unroll
        for (int j = 0; j < 9; j++) s[j] = 0.f;

#pragma unroll 4
        for (int d = 0; d < 64; d++) {
            float qv = qw[d];
            const float* kr = &Kt[d * SEQ + lane];
#pragma unroll
            for (int j = 0; j < 9; j++)
                s[j] += qv * kr[j * 32];
        }

        float mx = -1e30f;
#pragma unroll
        for (int j = 0; j < 9; j++) {
            int k = lane + j * 32;
            s[j] = (k < SEQ) ? s[j] * 0.125f : -1e30f;
            mx = fmaxf(mx, s[j]);
        }
        for (int off = 16; off; off >>= 1)
            mx = fmaxf(mx, __shfl_xor_sync(0xffffffffu, mx, off));

        float sum = 0.f;
#pragma unroll
        for (int j = 0; j < 9; j++) {
            float e = __expf(s[j] - mx);
            sum += e;
            s[j] = e;
        }
        for (int off = 16; off; off >>= 1)
            sum += __shfl_xor_sync(0xffffffffu, sum, off);
        float inv = 1.f / sum;
#pragma unroll
        for (int j = 0; j < 9; j++) {
            int k = lane + j * 32;
            if (k < SEQ) pw[k] = s[j] * inv;
        }
        __syncwarp();

        float o0 = 0.f, o1 = 0.f;
#pragma unroll 4
        for (int k = 0; k < SEQ; k++) {
            float pv = pw[k];
            float2 v2 = *(const float2*)&Vs[k * 64 + 2 * lane];
            o0 += pv * v2.x;
            o1 += pv * v2.y;
        }
        *(half2*)&O16[base + (size_t)q * D_ + 2 * lane] = __floats2half2_rn(o0, o1);
        __syncwarp();
    }
}

// ---------------- residual + LayerNorm ----------------
// OUT=0: write h fp32 + h16 fp16. OUT=1: scatter to aggregated/predictions (fp32 only).
template<int OUT>
__global__ void add_ln_kernel(const float* __restrict__ H, const float* __restrict__ Dl,
                              const float* __restrict__ g, const float* __restrict__ be,
                              float* __restrict__ Out, __half* __restrict__ Out16,
                              float* __restrict__ Pred)
{
    int row = blockIdx.x, tid = threadIdx.x;
    const float* hp = H  + (size_t)row * D_;
    const float* dp = Dl + (size_t)row * D_;
    float v0 = hp[tid]       + dp[tid];
    float v1 = hp[tid + 256] + dp[tid + 256];
    float v2 = hp[tid + 512] + dp[tid + 512];

    __shared__ float red[8];
    __shared__ float s_mu, s_var;
    int lane = tid & 31, w = tid >> 5;

    float s = v0 + v1 + v2;
    for (int off = 16; off; off >>= 1) s += __shfl_xor_sync(0xffffffffu, s, off);
    if (lane == 0) red[w] = s;
    __syncthreads();
    if (tid == 0) {
        float t = 0.f;
        for (int i = 0; i < 8; i++) t += red[i];
        s_mu = t * (1.0f / 768.0f);
    }
    __syncthreads();
    float mu = s_mu;
    float d0 = v0 - mu, d1 = v1 - mu, d2 = v2 - mu;
    float qv = d0 * d0 + d1 * d1 + d2 * d2;
    for (int off = 16; off; off >>= 1) qv += __shfl_xor_sync(0xffffffffu, qv, off);
    if (lane == 0) red[w] = qv;
    __syncthreads();
    if (tid == 0) {
        float t = 0.f;
        for (int i = 0; i < 8; i++) t += red[i];
        s_var = t * (1.0f / 768.0f);
    }
    __syncthreads();
    float rs = rsqrtf(s_var + 1e-6f);

    float o0 = d0 * rs * g[tid]       + be[tid];
    float o1 = d1 * rs * g[tid + 256] + be[tid + 256];
    float o2 = d2 * rs * g[tid + 512] + be[tid + 512];

    if (OUT == 0) {
        float*  op   = Out   + (size_t)row * D_;
        __half* op16 = Out16 + (size_t)row * D_;
        op[tid] = o0;        op16[tid] = __float2half(o0);
        op[tid + 256] = o1;  op16[tid + 256] = __float2half(o1);
        op[tid + 512] = o2;  op16[tid + 512] = __float2half(o2);
    } else {
        int b  = row / SEQ;
        int sp = row - b * SEQ;
        float* op = (sp == 0) ? (Out + (size_t)b * D_)
                              : (Pred + (size_t)(b * S_ + sp - 1) * D_);
        op[tid] = o0; op[tid + 256] = o1; op[tid + 512] = o2;
    }
}

// ---------------- host ----------------
static inline void run_hgemm(const __half* A, const __half* Bt, const float* bias,
                             float* C, __half* C16, int M, int N, int K, int mode)
{
    // mode 0: fp32 out; 1: fp32 out; 2: gelu + fp16 out
    dim3 grid(N / 256, (M + 127) / 128);
    if (mode == 2)      hgemm_kernel<1, 1><<<grid, 256, PG_SMEM>>>(A, Bt, bias, C, C16, M, N, K);
    else if (mode == 1) hgemm_kernel<0, 1><<<grid, 256, PG_SMEM>>>(A, Bt, bias, C, C16, M, N, K);
    else                hgemm_kernel<0, 0><<<grid, 256, PG_SMEM>>>(A, Bt, bias, C, C16, M, N, K);
}

extern "C" void kernel_launch(void* const* d_in, const int* in_sizes, int n_in,
                              void* d_out, int out_size)
{
    const float* inputs     = (const float*)d_in[0];
    const float* randomness = (const float*)d_in[1];
    const int*   perm       = (const int*)  d_in[2];
    const float* conv_w     = (const float*)d_in[3];
    const float* conv_b     = (const float*)d_in[4];
    const float* pos_emb    = (const float*)d_in[5];
    const float* mask_tok   = (const float*)d_in[6];
    const float* agg_tok    = (const float*)d_in[7];
    const float* wq  = (const float*)d_in[8];
    const float* bq  = (const float*)d_in[9];
    const float* wk  = (const float*)d_in[10];
    const float* bk  = (const float*)d_in[11];
    const float* wv  = (const float*)d_in[12];
    const float* bv  = (const float*)d_in[13];
    const float* wo  = (const float*)d_in[14];
    const float* bo  = (const float*)d_in[15];
    const float* ln1g = (const float*)d_in[16];
    const float* ln1b = (const float*)d_in[17];
    const float* w1  = (const float*)d_in[18];
    const float* b1  = (const float*)d_in[19];
    const float* w2  = (const float*)d_in[20];
    const float* b2  = (const float*)d_in[21];
    const float* ln2g = (const float*)d_in[22];
    const float* ln2b = (const float*)d_in[23];

    float* out      = (float*)d_out;
    float* out_agg  = out;
    float* out_pred = out + 49152;
    float* out_mask = out + 12632064;
    float* out_emb  = out + 12648448;

    float *h, *q, *k, *v, *t;
    __half *h16, *o16, *f16, *in16, *wt;
    cudaGetSymbolAddress((void**)&h,  g_h);
    cudaGetSymbolAddress((void**)&q,  g_q);
    cudaGetSymbolAddress((void**)&k,  g_k);
    cudaGetSymbolAddress((void**)&v,  g_v);
    cudaGetSymbolAddress((void**)&t,  g_t);
    cudaGetSymbolAddress((void**)&h16, g_h16);
    cudaGetSymbolAddress((void**)&o16, g_o16);
    cudaGetSymbolAddress((void**)&f16, g_f16);
    cudaGetSymbolAddress((void**)&in16, g_in16);
    cudaGetSymbolAddress((void**)&wt,  g_wt);

    cudaFuncSetAttribute(hgemm_kernel<0,0>, cudaFuncAttributeMaxDynamicSharedMemorySize, PG_SMEM);
    cudaFuncSetAttribute(hgemm_kernel<0,1>, cudaFuncAttributeMaxDynamicSharedMemorySize, PG_SMEM);
    cudaFuncSetAttribute(hgemm_kernel<1,1>, cudaFuncAttributeMaxDynamicSharedMemorySize, PG_SMEM);

    // prep: fp16 inputs + transposed fp16 weights
    in16_kernel<<<8192, 256>>>(inputs, in16, 2097152);
    {
        dim3 blk(32, 8);
        wt16_kernel<<<dim3(768/32, 512/32),  blk>>>(conv_w, wt + CW_OFF, 512, 768);
        for (int l = 0; l < 2; l++) {
            wt16_kernel<<<dim3(24, 24), blk>>>(wq + (size_t)l*589824, wt + WQ_OFF + (size_t)l*589824, 768, 768);
            wt16_kernel<<<dim3(24, 24), blk>>>(wk + (size_t)l*589824, wt + WK_OFF + (size_t)l*589824, 768, 768);
            wt16_kernel<<<dim3(24, 24), blk>>>(wv + (size_t)l*589824, wt + WV_OFF + (size_t)l*589824, 768, 768);
            wt16_kernel<<<dim3(24, 24), blk>>>(wo + (size_t)l*589824, wt + WO_OFF + (size_t)l*589824, 768, 768);
            wt16_kernel<<<dim3(96, 24), blk>>>(w1 + (size_t)l*2359296, wt + W1_OFF + (size_t)l*2359296, 768, 3072);
            wt16_kernel<<<dim3(24, 96), blk>>>(w2 + (size_t)l*2359296, wt + W2_OFF + (size_t)l*2359296, 3072, 768);
        }
    }

    // conv as GEMM (fp16 x fp16 -> fp32), writes embeddings output directly
    run_hgemm(in16, wt + CW_OFF, conv_b, out_emb, nullptr, BSR, D_, 512, 0);

    assemble_kernel<<<ROWS, 256>>>(out_emb, randomness, perm, mask_tok, agg_tok,
                                   pos_emb, h, h16, out_mask);

    const int SMEM_ATTN = (64 * SEQ + SEQ * 64 + 8 * SEQ + 8 * 64) * (int)sizeof(float);
    cudaFuncSetAttribute(attn_kernel, cudaFuncAttributeMaxDynamicSharedMemorySize, SMEM_ATTN);

    for (int l = 0; l < 2; l++) {
        const __half* wq_t = wt + WQ_OFF + (size_t)l * 589824;
        const __half* wk_t = wt + WK_OFF + (size_t)l * 589824;
        const __half* wv_t = wt + WV_OFF + (size_t)l * 589824;
        const __half* wo_t = wt + WO_OFF + (size_t)l * 589824;
        const __half* w1_t = wt + W1_OFF + (size_t)l * 2359296;
        const __half* w2_t = wt + W2_OFF + (size_t)l * 2359296;

        run_hgemm(h16, wq_t, bq + l * D_, q, nullptr, ROWS, D_, D_, 0);
        run_hgemm(h16, wk_t, bk + l * D_, k, nullptr, ROWS, D_, D_, 0);
        run_hgemm(h16, wv_t, bv + l * D_, v, nullptr, ROWS, D_, D_, 0);

        attn_kernel<<<dim3(HEADS, B_), 256, SMEM_ATTN>>>(q, k, v, o16);

        run_hgemm(o16, wo_t, bo + l * D_, t, nullptr, ROWS, D_, D_, 0);
        add_ln_kernel<0><<<ROWS, 256>>>(h, t, ln1g + l * D_, ln1b + l * D_, h, h16, nullptr);

        run_hgemm(h16, w1_t, b1 + l * F_, nullptr, f16, ROWS, F_, D_, 2);
        run_hgemm(f16, w2_t, b2 + l * D_, t, nullptr, ROWS, D_, F_, 0);
        if (l == 0)
            add_ln_kernel<0><<<ROWS, 256>>>(h, t, ln2g + l * D_, ln2b + l * D_, h, h16, nullptr);
        else
            add_ln_kernel<1><<<ROWS, 256>>>(h, t, ln2g + l * D_, ln2b + l * D_, out_agg, nullptr, out_pred);
    }
}

// round 9
// speedup vs baseline: 2.5727x; 1.7454x over previous
#include <cuda_runtime.h>
#include <cuda_fp16.h>
#include <math.h>
#include <stdint.h>

#define B_    64
#define SEQ   257
#define S_    256
#define D_    768
#define F_    3072
#define HEADS 12
#define DKH   64
#define ROWS  (B_*SEQ)     // 16448
#define BSR   (B_*S_)      // 16384

// ---------------- scratch ----------------
__device__ float  g_h [(size_t)ROWS*D_];
__device__ float  g_t [(size_t)ROWS*D_];
__device__ __half g_h16[(size_t)ROWS*D_];
__device__ __half g_o16[(size_t)ROWS*D_];
__device__ __half g_f16[(size_t)ROWS*F_];
__device__ __half g_qkv16[(size_t)ROWS*2304];
__device__ __half g_in16[(size_t)BSR*512];
__device__ __half g_wt[14548992];        // fp16 transposed weights [N][K]
__device__ float  g_biasqkv[2*2304];

// half offsets in g_wt
#define CW_OFF  0
#define QKV_OFF 393216          // 2 layers x 2304x768
#define WO_OFF  3932160
#define W1_OFF  5111808
#define W2_OFF  9830400

__device__ __forceinline__ float gelu_f(float x) {
    float x3 = x * x * x;
    float t = tanhf(0.7978845608028654f * (x + 0.044715f * x3));
    return 0.5f * x * (1.0f + t);
}

// ---------------- prep ----------------
__global__ void in16_kernel(const float* __restrict__ src, __half* __restrict__ dst, int n4)
{
    int i = blockIdx.x * 256 + threadIdx.x;
    if (i < n4) {
        float4 v = ((const float4*)src)[i];
        ((half2*)dst)[2 * i]     = __floats2half2_rn(v.x, v.y);
        ((half2*)dst)[2 * i + 1] = __floats2half2_rn(v.z, v.w);
    }
}

__global__ void wt16_kernel(const float* __restrict__ src, __half* __restrict__ dst, int K, int N)
{
    __shared__ float tile[32][33];
    int k0 = blockIdx.y * 32, n0 = blockIdx.x * 32;
    int tx = threadIdx.x, ty = threadIdx.y;     // 32 x 8
#pragma unroll
    for (int i = 0; i < 4; i++)
        tile[ty + i * 8][tx] = src[(size_t)(k0 + ty + i * 8) * N + n0 + tx];
    __syncthreads();
#pragma unroll
    for (int i = 0; i < 4; i++)
        dst[(size_t)(n0 + ty + i * 8) * K + k0 + tx] = __float2half(tile[tx][ty + i * 8]);
}

__global__ void biascat_kernel(const float* __restrict__ bq, const float* __restrict__ bk,
                               const float* __restrict__ bv, float* __restrict__ dst)
{
    int l = blockIdx.x;
    int t = threadIdx.x;
#pragma unroll
    for (int e = 0; e < 3; e++) {
        int d = t + e * 256;
        dst[l * 2304 + d]        = bq[l * 768 + d];
        dst[l * 2304 + 768 + d]  = bk[l * 768 + d];
        dst[l * 2304 + 1536 + d] = bv[l * 768 + d];
    }
}

// ================= cp.async 5-stage FP16 GEMM (128x256, BK=32) =================
#define PG_STAGES   5
#define PG_ASTAGE_B (128*80)
#define PG_BSTAGE_B (256*80)
#define PG_BBASE    (PG_STAGES*PG_ASTAGE_B)
#define PG_SMEM     (PG_STAGES*(PG_ASTAGE_B+PG_BSTAGE_B))

__device__ __forceinline__ void cp16h(uint32_t dst, const __half* src, int sz) {
    asm volatile("cp.async.cg.shared.global [%0], [%1], 16, %2;"
                 :: "r"(dst), "l"(src), "r"(sz) : "memory");
}

template<int ACT, int OUTHALF>
__global__ void __launch_bounds__(256, 1)
hgemm_kernel(const __half* __restrict__ A, const __half* __restrict__ Bt,
             const float* __restrict__ bias, float* __restrict__ C,
             __half* __restrict__ C16, int M, int N, int K)
{
    extern __shared__ char dsm[];
    const uint32_t sbase = (uint32_t)__cvta_generic_to_shared(dsm);

    const int tid  = threadIdx.x;
    const int bm   = blockIdx.y * 128;
    const int bn   = blockIdx.x * 256;
    const int wid  = tid >> 5;
    const int lane = tid & 31;
    const int wm   = (wid & 1) * 64;
    const int wn   = (wid >> 1) * 64;
    const int g    = lane >> 2;
    const int tig  = lane & 3;

    float acc[4][8][4];
#pragma unroll
    for (int i = 0; i < 4; i++)
#pragma unroll
        for (int j = 0; j < 8; j++)
#pragma unroll
            for (int c = 0; c < 4; c++) acc[i][j][c] = 0.f;

    const int arow = tid >> 1;
    const bool aval = (bm + arow) < M;
    const __half* Asrc = A + (size_t)(aval ? (bm + arow) : 0) * K + (tid & 1) * 16;
    const uint32_t adst = sbase + arow * 80 + (tid & 1) * 32;
    const int asz = aval ? 16 : 0;

    const __half* Bsrc = Bt + (size_t)(bn + tid) * K;
    const uint32_t bdst = sbase + PG_BBASE + tid * 80;

    const int nk = K / 32;

#define PG_ISSUE(kt, s)                                                         \
    {                                                                           \
        const __half* as_ = Asrc + (kt) * 32;                                   \
        uint32_t ad_ = adst + (s) * PG_ASTAGE_B;                                \
        cp16h(ad_, as_, asz); cp16h(ad_ + 16, as_ + 8, asz);                    \
        const __half* bs_ = Bsrc + (kt) * 32;                                   \
        uint32_t bd_ = bdst + (s) * PG_BSTAGE_B;                                \
        cp16h(bd_,      bs_,      16); cp16h(bd_ + 16, bs_ + 8,  16);           \
        cp16h(bd_ + 32, bs_ + 16, 16); cp16h(bd_ + 48, bs_ + 24, 16);           \
    }

#pragma unroll
    for (int s = 0; s < PG_STAGES - 1; s++) {
        PG_ISSUE(s, s);
        asm volatile("cp.async.commit_group;" ::: "memory");
    }

    for (int kt = 0; kt < nk; kt++) {
        const int buf = kt % PG_STAGES;
        asm volatile("cp.async.wait_group %0;" :: "n"(PG_STAGES - 2) : "memory");
        __syncthreads();

        const int nt = kt + PG_STAGES - 1;
        if (nt < nk) { PG_ISSUE(nt, nt % PG_STAGES); }
        asm volatile("cp.async.commit_group;" ::: "memory");

        const uint32_t* Aw = (const uint32_t*)(dsm + buf * PG_ASTAGE_B);
        const uint32_t* Bw = (const uint32_t*)(dsm + PG_BBASE + buf * PG_BSTAGE_B);
#pragma unroll
        for (int kk = 0; kk < 2; kk++) {
            const int kw = kk * 8 + tig;
            uint32_t bf0[8], bf1[8];
#pragma unroll
            for (int j = 0; j < 8; j++) {
                const int n0 = wn + j * 8 + g;
                bf0[j] = Bw[n0 * 20 + kw];
                bf1[j] = Bw[n0 * 20 + kw + 4];
            }
#pragma unroll
            for (int i = 0; i < 4; i++) {
                const int r = wm + i * 16 + g;
                uint32_t a0 = Aw[r * 20 + kw];
                uint32_t a1 = Aw[(r + 8) * 20 + kw];
                uint32_t a2 = Aw[r * 20 + kw + 4];
                uint32_t a3 = Aw[(r + 8) * 20 + kw + 4];
#pragma unroll
                for (int j = 0; j < 8; j++) {
                    asm volatile(
                        "mma.sync.aligned.m16n8k16.row.col.f32.f16.f16.f32 "
                        "{%0,%1,%2,%3}, {%4,%5,%6,%7}, {%8,%9}, {%0,%1,%2,%3};"
                        : "+f"(acc[i][j][0]), "+f"(acc[i][j][1]),
                          "+f"(acc[i][j][2]), "+f"(acc[i][j][3])
                        : "r"(a0), "r"(a1), "r"(a2), "r"(a3),
                          "r"(bf0[j]), "r"(bf1[j]));
                }
            }
        }
    }

#pragma unroll
    for (int i = 0; i < 4; i++) {
        const int r0 = bm + wm + i * 16 + g;
        const int r1 = r0 + 8;
#pragma unroll
        for (int j = 0; j < 8; j++) {
            const int col = bn + wn + j * 8 + 2 * tig;
            const float bv0 = bias[col];
            const float bv1 = bias[col + 1];
            float v0a = acc[i][j][0] + bv0;
            float v1a = acc[i][j][1] + bv1;
            float v2a = acc[i][j][2] + bv0;
            float v3a = acc[i][j][3] + bv1;
            if (ACT == 1) { v0a = gelu_f(v0a); v1a = gelu_f(v1a); v2a = gelu_f(v2a); v3a = gelu_f(v3a); }
            if (OUTHALF) {
                if (r0 < M) *(half2*)&C16[(size_t)r0 * N + col] = __floats2half2_rn(v0a, v1a);
                if (r1 < M) *(half2*)&C16[(size_t)r1 * N + col] = __floats2half2_rn(v2a, v3a);
            } else {
                if (r0 < M) *(float2*)&C[(size_t)r0 * N + col] = make_float2(v0a, v1a);
                if (r1 < M) *(float2*)&C[(size_t)r1 * N + col] = make_float2(v2a, v3a);
            }
        }
    }
}

// ---------------- assemble h (+fp16 copy) ----------------
__global__ void assemble_kernel(const float* __restrict__ x,
                                const float* __restrict__ rnd,
                                const int*   __restrict__ perm,
                                const float* __restrict__ mask_tok,
                                const float* __restrict__ agg_tok,
                                const float* __restrict__ pos_emb,
                                float* __restrict__ h, __half* __restrict__ h16,
                                float* __restrict__ mask_pos)
{
    int row = blockIdx.x;
    int b   = row / SEQ;
    int sp  = row - b * SEQ;
    int tid = threadIdx.x;
    float*  hp  = h   + (size_t)row * D_;
    __half* hp16 = h16 + (size_t)row * D_;

    if (sp == 0) {
#pragma unroll
        for (int e = 0; e < 3; e++) {
            int d = tid + e * 256;
            float v = agg_tok[d];
            hp[d] = v; hp16[d] = __float2half(v);
        }
        return;
    }
    int s = sp - 1;
    int i = b * S_ + s;
    float r0 = rnd[i * 3 + 0];
    float r1 = rnd[i * 3 + 1];
    float r2 = rnd[i * 3 + 2];
    bool  sel = (r0 <= 0.2f);
    float m  = (sel && r1 <= 0.8f) ? 1.f : 0.f;
    float rd = (sel && r1 > 0.8f && r2 <= 0.5f) ? 1.f : 0.f;
    if (tid == 0) mask_pos[i] = sel ? 1.f : 0.f;

    int pi = perm[i];
    const float* xp = x + (size_t)i  * D_;
    const float* sh = x + (size_t)pi * D_;
    const float* pe = pos_emb + (size_t)s * D_;
    float keep = 1.f - m - rd;

#pragma unroll
    for (int e = 0; e < 3; e++) {
        int d = tid + e * 256;
        float v = xp[d] * keep + mask_tok[d] * m + sh[d] * rd + pe[d];
        hp[d] = v; hp16[d] = __float2half(v);
    }
}

// ================= tensor-core flash attention =================
// One block per (head, batch). qkv16: [ROWS][2304] fp16 = [q|k|v].
// smem: Ks[288][72] halves + Vt[64][296] halves. 8 warps x 16-row q tiles.
#define SP     288
#define KSTR   72      // halves per Ks row
#define VSTR   296     // halves per Vt row
#define ATTN_SMEM (SP*KSTR*2 + 64*VSTR*2)

__global__ void __launch_bounds__(256)
attn_kernel(const __half* __restrict__ qkv, __half* __restrict__ O16)
{
    extern __shared__ char asm_[];
    __half* Ks = (__half*)asm_;                    // [288][72]
    __half* Vt = (__half*)(asm_ + SP * KSTR * 2);  // [64][296]

    const int hh = blockIdx.x;
    const int bb = blockIdx.y;
    const int tid = threadIdx.x;
    const int wid = tid >> 5;
    const int lane = tid & 31;
    const int g = lane >> 2;
    const int tig = lane & 3;
    const int brow = bb * SEQ;

    // load K [257][64] -> Ks (half2 coalesced)
    for (int idx = tid; idx < SEQ * 32; idx += 256) {
        int seq = idx >> 5, d2 = idx & 31;
        half2 v = *(const half2*)&qkv[(size_t)(brow + seq) * 2304 + 768 + hh * 64 + d2 * 2];
        *(half2*)&Ks[seq * KSTR + d2 * 2] = v;
    }
    // zero Vt padding cols 256..295
    for (int idx = tid; idx < 64 * 20; idx += 256) {
        int d = idx / 20, w = idx % 20;
        *(half2*)&Vt[d * VSTR + 256 + w * 2] = __floats2half2_rn(0.f, 0.f);
    }
    // load V transposed
    for (int idx = tid; idx < SEQ * 64; idx += 256) {
        int seq = idx >> 6, d = idx & 63;
        Vt[d * VSTR + seq] = qkv[(size_t)(brow + seq) * 2304 + 1536 + hh * 64 + d];
    }
    __syncthreads();

    const uint32_t* Kw = (const uint32_t*)Ks;
    const uint32_t* Vw = (const uint32_t*)Vt;

    for (int qt = wid; qt < 17; qt += 8) {
        // Q fragments (clamp rows; masked at store)
        int qr0 = qt * 16 + g;     if (qr0 > 256) qr0 = 256;
        int qr1 = qt * 16 + 8 + g; if (qr1 > 256) qr1 = 256;
        const __half* q0 = qkv + (size_t)(brow + qr0) * 2304 + hh * 64;
        const __half* q1 = qkv + (size_t)(brow + qr1) * 2304 + hh * 64;
        uint32_t aq[4][4];
#pragma unroll
        for (int kc = 0; kc < 4; kc++) {
            int cb = kc * 16 + 2 * tig;
            aq[kc][0] = *(const uint32_t*)(q0 + cb);
            aq[kc][1] = *(const uint32_t*)(q1 + cb);
            aq[kc][2] = *(const uint32_t*)(q0 + cb + 8);
            aq[kc][3] = *(const uint32_t*)(q1 + cb + 8);
        }

        float m0 = -1e30f, m1 = -1e30f, l0 = 0.f, l1 = 0.f;
        float o[8][4];
#pragma unroll
        for (int nt = 0; nt < 8; nt++)
#pragma unroll
            for (int c = 0; c < 4; c++) o[nt][c] = 0.f;

#pragma unroll
        for (int ch = 0; ch < 2; ch++) {
            float sc[18][4];
#pragma unroll
            for (int j = 0; j < 18; j++)
#pragma unroll
                for (int c = 0; c < 4; c++) sc[j][c] = 0.f;

#pragma unroll
            for (int j = 0; j < 18; j++) {
                const int n0 = ch * 144 + j * 8 + g;
#pragma unroll
                for (int kc = 0; kc < 4; kc++) {
                    uint32_t b0 = Kw[n0 * (KSTR / 2) + kc * 8 + tig];
                    uint32_t b1 = Kw[n0 * (KSTR / 2) + kc * 8 + tig + 4];
                    asm volatile(
                        "mma.sync.aligned.m16n8k16.row.col.f32.f16.f16.f32 "
                        "{%0,%1,%2,%3}, {%4,%5,%6,%7}, {%8,%9}, {%0,%1,%2,%3};"
                        : "+f"(sc[j][0]), "+f"(sc[j][1]), "+f"(sc[j][2]), "+f"(sc[j][3])
                        : "r"(aq[kc][0]), "r"(aq[kc][1]), "r"(aq[kc][2]), "r"(aq[kc][3]),
                          "r"(b0), "r"(b1));
                }
            }

            // scale + mask
            float mx0 = -1e30f, mx1 = -1e30f;
#pragma unroll
            for (int j = 0; j < 18; j++) {
                int c0 = ch * 144 + j * 8 + 2 * tig;
                sc[j][0] = (c0     < SEQ) ? sc[j][0] * 0.125f : -1e30f;
                sc[j][1] = (c0 + 1 < SEQ) ? sc[j][1] * 0.125f : -1e30f;
                sc[j][2] = (c0     < SEQ) ? sc[j][2] * 0.125f : -1e30f;
                sc[j][3] = (c0 + 1 < SEQ) ? sc[j][3] * 0.125f : -1e30f;
                mx0 = fmaxf(mx0, fmaxf(sc[j][0], sc[j][1]));
                mx1 = fmaxf(mx1, fmaxf(sc[j][2], sc[j][3]));
            }
            mx0 = fmaxf(mx0, __shfl_xor_sync(0xffffffffu, mx0, 1));
            mx0 = fmaxf(mx0, __shfl_xor_sync(0xffffffffu, mx0, 2));
            mx1 = fmaxf(mx1, __shfl_xor_sync(0xffffffffu, mx1, 1));
            mx1 = fmaxf(mx1, __shfl_xor_sync(0xffffffffu, mx1, 2));

            float mn0 = fmaxf(m0, mx0), mn1 = fmaxf(m1, mx1);
            float sc0 = __expf(m0 - mn0), sc1 = __expf(m1 - mn1);
            m0 = mn0; m1 = mn1;

            float sum0 = 0.f, sum1 = 0.f;
#pragma unroll
            for (int j = 0; j < 18; j++) {
                sc[j][0] = __expf(sc[j][0] - mn0);
                sc[j][1] = __expf(sc[j][1] - mn0);
                sc[j][2] = __expf(sc[j][2] - mn1);
                sc[j][3] = __expf(sc[j][3] - mn1);
                sum0 += sc[j][0] + sc[j][1];
                sum1 += sc[j][2] + sc[j][3];
            }
            sum0 += __shfl_xor_sync(0xffffffffu, sum0, 1);
            sum0 += __shfl_xor_sync(0xffffffffu, sum0, 2);
            sum1 += __shfl_xor_sync(0xffffffffu, sum1, 1);
            sum1 += __shfl_xor_sync(0xffffffffu, sum1, 2);
            l0 = l0 * sc0 + sum0;
            l1 = l1 * sc1 + sum1;

#pragma unroll
            for (int nt = 0; nt < 8; nt++) {
                o[nt][0] *= sc0; o[nt][1] *= sc0;
                o[nt][2] *= sc1; o[nt][3] *= sc1;
            }

            // PV: 9 k-chunks of 16
#pragma unroll
            for (int kc = 0; kc < 9; kc++) {
                half2 pa0 = __floats2half2_rn(sc[2*kc][0],   sc[2*kc][1]);
                half2 pa1 = __floats2half2_rn(sc[2*kc][2],   sc[2*kc][3]);
                half2 pa2 = __floats2half2_rn(sc[2*kc+1][0], sc[2*kc+1][1]);
                half2 pa3 = __floats2half2_rn(sc[2*kc+1][2], sc[2*kc+1][3]);
                uint32_t ua0 = *(uint32_t*)&pa0, ua1 = *(uint32_t*)&pa1;
                uint32_t ua2 = *(uint32_t*)&pa2, ua3 = *(uint32_t*)&pa3;
                const int kb2 = (ch * 144 + kc * 16) / 2;
#pragma unroll
                for (int nt = 0; nt < 8; nt++) {
                    const int vr = nt * 8 + g;
                    uint32_t b0 = Vw[vr * (VSTR / 2) + kb2 + tig];
                    uint32_t b1 = Vw[vr * (VSTR / 2) + kb2 + tig + 4];
                    asm volatile(
                        "mma.sync.aligned.m16n8k16.row.col.f32.f16.f16.f32 "
                        "{%0,%1,%2,%3}, {%4,%5,%6,%7}, {%8,%9}, {%0,%1,%2,%3};"
                        : "+f"(o[nt][0]), "+f"(o[nt][1]), "+f"(o[nt][2]), "+f"(o[nt][3])
                        : "r"(ua0), "r"(ua1), "r"(ua2), "r"(ua3),
                          "r"(b0), "r"(b1));
                }
            }
        }

        float inv0 = 1.f / l0, inv1 = 1.f / l1;
        int r0 = qt * 16 + g, r1 = r0 + 8;
#pragma unroll
        for (int nt = 0; nt < 8; nt++) {
            int col = hh * 64 + nt * 8 + 2 * tig;
            if (r0 < SEQ)
                *(half2*)&O16[(size_t)(brow + r0) * 768 + col] =
                    __floats2half2_rn(o[nt][0] * inv0, o[nt][1] * inv0);
            if (r1 < SEQ)
                *(half2*)&O16[(size_t)(brow + r1) * 768 + col] =
                    __floats2half2_rn(o[nt][2] * inv1, o[nt][3] * inv1);
        }
    }
}

// ---------------- residual + LayerNorm ----------------
template<int OUT>
__global__ void add_ln_kernel(const float* __restrict__ H, const float* __restrict__ Dl,
                              const float* __restrict__ g, const float* __restrict__ be,
                              float* __restrict__ Out, __half* __restrict__ Out16,
                              float* __restrict__ Pred)
{
    int row = blockIdx.x, tid = threadIdx.x;
    const float* hp = H  + (size_t)row * D_;
    const float* dp = Dl + (size_t)row * D_;
    float v0 = hp[tid]       + dp[tid];
    float v1 = hp[tid + 256] + dp[tid + 256];
    float v2 = hp[tid + 512] + dp[tid + 512];

    __shared__ float red[8];
    __shared__ float s_mu, s_var;
    int lane = tid & 31, w = tid >> 5;

    float s = v0 + v1 + v2;
    for (int off = 16; off; off >>= 1) s += __shfl_xor_sync(0xffffffffu, s, off);
    if (lane == 0) red[w] = s;
    __syncthreads();
    if (tid == 0) {
        float t = 0.f;
        for (int i = 0; i < 8; i++) t += red[i];
        s_mu = t * (1.0f / 768.0f);
    }
    __syncthreads();
    float mu = s_mu;
    float d0 = v0 - mu, d1 = v1 - mu, d2 = v2 - mu;
    float qv = d0 * d0 + d1 * d1 + d2 * d2;
    for (int off = 16; off; off >>= 1) qv += __shfl_xor_sync(0xffffffffu, qv, off);
    if (lane == 0) red[w] = qv;
    __syncthreads();
    if (tid == 0) {
        float t = 0.f;
        for (int i = 0; i < 8; i++) t += red[i];
        s_var = t * (1.0f / 768.0f);
    }
    __syncthreads();
    float rs = rsqrtf(s_var + 1e-6f);

    float o0 = d0 * rs * g[tid]       + be[tid];
    float o1 = d1 * rs * g[tid + 256] + be[tid + 256];
    float o2 = d2 * rs * g[tid + 512] + be[tid + 512];

    if (OUT == 0) {
        float*  op   = Out   + (size_t)row * D_;
        __half* op16 = Out16 + (size_t)row * D_;
        op[tid] = o0;        op16[tid] = __float2half(o0);
        op[tid + 256] = o1;  op16[tid + 256] = __float2half(o1);
        op[tid + 512] = o2;  op16[tid + 512] = __float2half(o2);
    } else {
        int b  = row / SEQ;
        int sp = row - b * SEQ;
        float* op = (sp == 0) ? (Out + (size_t)b * D_)
                              : (Pred + (size_t)(b * S_ + sp - 1) * D_);
        op[tid] = o0; op[tid + 256] = o1; op[tid + 512] = o2;
    }
}

// ---------------- host ----------------
static inline void run_hgemm(const __half* A, const __half* Bt, const float* bias,
                             float* C, __half* C16, int M, int N, int K, int mode)
{
    dim3 grid(N / 256, (M + 127) / 128);
    if (mode == 2)      hgemm_kernel<1, 1><<<grid, 256, PG_SMEM>>>(A, Bt, bias, C, C16, M, N, K);
    else if (mode == 1) hgemm_kernel<0, 1><<<grid, 256, PG_SMEM>>>(A, Bt, bias, C, C16, M, N, K);
    else                hgemm_kernel<0, 0><<<grid, 256, PG_SMEM>>>(A, Bt, bias, C, C16, M, N, K);
}

extern "C" void kernel_launch(void* const* d_in, const int* in_sizes, int n_in,
                              void* d_out, int out_size)
{
    const float* inputs     = (const float*)d_in[0];
    const float* randomness = (const float*)d_in[1];
    const int*   perm       = (const int*)  d_in[2];
    const float* conv_w     = (const float*)d_in[3];
    const float* conv_b     = (const float*)d_in[4];
    const float* pos_emb    = (const float*)d_in[5];
    const float* mask_tok   = (const float*)d_in[6];
    const float* agg_tok    = (const float*)d_in[7];
    const float* wq  = (const float*)d_in[8];
    const float* bq  = (const float*)d_in[9];
    const float* wk  = (const float*)d_in[10];
    const float* bk  = (const float*)d_in[11];
    const float* wv  = (const float*)d_in[12];
    const float* bv  = (const float*)d_in[13];
    const float* wo  = (const float*)d_in[14];
    const float* bo  = (const float*)d_in[15];
    const float* ln1g = (const float*)d_in[16];
    const float* ln1b = (const float*)d_in[17];
    const float* w1  = (const float*)d_in[18];
    const float* b1  = (const float*)d_in[19];
    const float* w2  = (const float*)d_in[20];
    const float* b2  = (const float*)d_in[21];
    const float* ln2g = (const float*)d_in[22];
    const float* ln2b = (const float*)d_in[23];

    float* out      = (float*)d_out;
    float* out_agg  = out;
    float* out_pred = out + 49152;
    float* out_mask = out + 12632064;
    float* out_emb  = out + 12648448;

    float *h, *t, *biasqkv;
    __half *h16, *o16, *f16, *qkv16, *in16, *wt;
    cudaGetSymbolAddress((void**)&h,  g_h);
    cudaGetSymbolAddress((void**)&t,  g_t);
    cudaGetSymbolAddress((void**)&h16, g_h16);
    cudaGetSymbolAddress((void**)&o16, g_o16);
    cudaGetSymbolAddress((void**)&f16, g_f16);
    cudaGetSymbolAddress((void**)&qkv16, g_qkv16);
    cudaGetSymbolAddress((void**)&in16, g_in16);
    cudaGetSymbolAddress((void**)&wt,  g_wt);
    cudaGetSymbolAddress((void**)&biasqkv, g_biasqkv);

    cudaFuncSetAttribute(hgemm_kernel<0,0>, cudaFuncAttributeMaxDynamicSharedMemorySize, PG_SMEM);
    cudaFuncSetAttribute(hgemm_kernel<0,1>, cudaFuncAttributeMaxDynamicSharedMemorySize, PG_SMEM);
    cudaFuncSetAttribute(hgemm_kernel<1,1>, cudaFuncAttributeMaxDynamicSharedMemorySize, PG_SMEM);
    cudaFuncSetAttribute(attn_kernel, cudaFuncAttributeMaxDynamicSharedMemorySize, ATTN_SMEM);

    // prep
    in16_kernel<<<8192, 256>>>(inputs, in16, 2097152);
    biascat_kernel<<<2, 256>>>(bq, bk, bv, biasqkv);
    {
        dim3 blk(32, 8);
        wt16_kernel<<<dim3(24, 16), blk>>>(conv_w, wt + CW_OFF, 512, 768);
        for (int l = 0; l < 2; l++) {
            __half* qkvw = wt + QKV_OFF + (size_t)l * 1769472;
            wt16_kernel<<<dim3(24, 24), blk>>>(wq + (size_t)l*589824, qkvw,          768, 768);
            wt16_kernel<<<dim3(24, 24), blk>>>(wk + (size_t)l*589824, qkvw + 589824, 768, 768);
            wt16_kernel<<<dim3(24, 24), blk>>>(wv + (size_t)l*589824, qkvw + 1179648,768, 768);
            wt16_kernel<<<dim3(24, 24), blk>>>(wo + (size_t)l*589824, wt + WO_OFF + (size_t)l*589824, 768, 768);
            wt16_kernel<<<dim3(96, 24), blk>>>(w1 + (size_t)l*2359296, wt + W1_OFF + (size_t)l*2359296, 768, 3072);
            wt16_kernel<<<dim3(24, 96), blk>>>(w2 + (size_t)l*2359296, wt + W2_OFF + (size_t)l*2359296, 3072, 768);
        }
    }

    // conv as GEMM, writes embeddings output directly
    run_hgemm(in16, wt + CW_OFF, conv_b, out_emb, nullptr, BSR, D_, 512, 0);

    assemble_kernel<<<ROWS, 256>>>(out_emb, randomness, perm, mask_tok, agg_tok,
                                   pos_emb, h, h16, out_mask);

    for (int l = 0; l < 2; l++) {
        const __half* qkvw = wt + QKV_OFF + (size_t)l * 1769472;
        const __half* wo_t = wt + WO_OFF + (size_t)l * 589824;
        const __half* w1_t = wt + W1_OFF + (size_t)l * 2359296;
        const __half* w2_t = wt + W2_OFF + (size_t)l * 2359296;

        // fused QKV GEMM -> fp16 [ROWS][2304]
        run_hgemm(h16, qkvw, biasqkv + l * 2304, nullptr, qkv16, ROWS, 2304, D_, 1);

        attn_kernel<<<dim3(HEADS, B_), 256, ATTN_SMEM>>>(qkv16, o16);

        run_hgemm(o16, wo_t, bo + l * D_, t, nullptr, ROWS, D_, D_, 0);
        add_ln_kernel<0><<<ROWS, 256>>>(h, t, ln1g + l * D_, ln1b + l * D_, h, h16, nullptr);

        run_hgemm(h16, w1_t, b1 + l * F_, nullptr, f16, ROWS, F_, D_, 2);
        run_hgemm(f16, w2_t, b2 + l * D_, t, nullptr, ROWS, D_, F_, 0);
        if (l == 0)
            add_ln_kernel<0><<<ROWS, 256>>>(h, t, ln2g + l * D_, ln2b + l * D_, h, h16, nullptr);
        else
            add_ln_kernel<1><<<ROWS, 256>>>(h, t, ln2g + l * D_, ln2b + l * D_, out_agg, nullptr, out_pred);
    }
}

// round 10
// speedup vs baseline: 2.5733x; 1.0002x over previous
#include <cuda_runtime.h>
#include <cuda_fp16.h>
#include <math.h>
#include <stdint.h>

#define B_    64
#define SEQ   257
#define S_    256
#define D_    768
#define F_    3072
#define HEADS 12
#define DKH   64
#define ROWS  (B_*SEQ)     // 16448
#define BSR   (B_*S_)      // 16384

// ---------------- scratch ----------------
__device__ float  g_h [(size_t)ROWS*D_];
__device__ __half g_h16[(size_t)ROWS*D_];
__device__ __half g_t16[(size_t)ROWS*D_];
__device__ __half g_o16[(size_t)ROWS*D_];
__device__ __half g_f16[(size_t)ROWS*F_];
__device__ __half g_qkv16[(size_t)ROWS*2304];
__device__ __half g_in16[(size_t)BSR*512];
__device__ __half g_wt[14548992];        // fp16 transposed weights [N][K]
__device__ float  g_biasqkv[2*2304];

// half offsets in g_wt
#define CW_OFF  0
#define QKV_OFF 393216          // 2 layers x 2304x768
#define WO_OFF  3932160
#define W1_OFF  5111808
#define W2_OFF  9830400

__device__ __forceinline__ float gelu_f(float x) {
    float x3 = x * x * x;
    float t = tanhf(0.7978845608028654f * (x + 0.044715f * x3));
    return 0.5f * x * (1.0f + t);
}

// ---------------- prep ----------------
__global__ void in16_kernel(const float* __restrict__ src, __half* __restrict__ dst, int n4)
{
    int i = blockIdx.x * 256 + threadIdx.x;
    if (i < n4) {
        float4 v = ((const float4*)src)[i];
        ((half2*)dst)[2 * i]     = __floats2half2_rn(v.x, v.y);
        ((half2*)dst)[2 * i + 1] = __floats2half2_rn(v.z, v.w);
    }
}

// transpose+convert [K][N] fp32 -> [N][K] fp16; z-batched with strides
__global__ void wt16_kernel(const float* __restrict__ src0, __half* __restrict__ dst0,
                            int K, int N, size_t zsrc, size_t zdst)
{
    __shared__ float tile[32][33];
    const float* src = src0 + (size_t)blockIdx.z * zsrc;
    __half* dst = dst0 + (size_t)blockIdx.z * zdst;
    int k0 = blockIdx.y * 32, n0 = blockIdx.x * 32;
    int tx = threadIdx.x, ty = threadIdx.y;     // 32 x 8
#pragma unroll
    for (int i = 0; i < 4; i++)
        tile[ty + i * 8][tx] = src[(size_t)(k0 + ty + i * 8) * N + n0 + tx];
    __syncthreads();
#pragma unroll
    for (int i = 0; i < 4; i++)
        dst[(size_t)(n0 + ty + i * 8) * K + k0 + tx] = __float2half(tile[tx][ty + i * 8]);
}

__global__ void biascat_kernel(const float* __restrict__ bq, const float* __restrict__ bk,
                               const float* __restrict__ bv, float* __restrict__ dst)
{
    int l = blockIdx.x;
    int t = threadIdx.x;
#pragma unroll
    for (int e = 0; e < 3; e++) {
        int d = t + e * 256;
        dst[l * 2304 + d]        = bq[l * 768 + d];
        dst[l * 2304 + 768 + d]  = bk[l * 768 + d];
        dst[l * 2304 + 1536 + d] = bv[l * 768 + d];
    }
}

// ================= cp.async 4-stage FP16 GEMM (128x256, BK=64) =================
#define PG_STAGES   4
#define PG_ASTAGE_B (128*144)     // 128 rows x 72 halves
#define PG_BSTAGE_B (256*144)     // 256 rows x 72 halves
#define PG_BBASE    (PG_STAGES*PG_ASTAGE_B)
#define PG_SMEM     (PG_STAGES*(PG_ASTAGE_B+PG_BSTAGE_B))   // 221184

__device__ __forceinline__ void cp16h(uint32_t dst, const __half* src, int sz) {
    asm volatile("cp.async.cg.shared.global [%0], [%1], 16, %2;"
                 :: "r"(dst), "l"(src), "r"(sz) : "memory");
}

template<int ACT, int OUTHALF>
__global__ void __launch_bounds__(256, 1)
hgemm_kernel(const __half* __restrict__ A, const __half* __restrict__ Bt,
             const float* __restrict__ bias, float* __restrict__ C,
             __half* __restrict__ C16, int M, int N, int K)
{
    extern __shared__ char dsm[];
    const uint32_t sbase = (uint32_t)__cvta_generic_to_shared(dsm);

    const int tid  = threadIdx.x;
    const int bm   = blockIdx.y * 128;
    const int bn   = blockIdx.x * 256;
    const int wid  = tid >> 5;
    const int lane = tid & 31;
    const int wm   = (wid & 1) * 64;
    const int wn   = (wid >> 1) * 64;
    const int g    = lane >> 2;
    const int tig  = lane & 3;

    float acc[4][8][4];
#pragma unroll
    for (int i = 0; i < 4; i++)
#pragma unroll
        for (int j = 0; j < 8; j++)
#pragma unroll
            for (int c = 0; c < 4; c++) acc[i][j][c] = 0.f;

    // producers: A: 2 threads/row, 64B each; B: 1 thread/row, 128B
    const int arow = tid >> 1;
    const int achk = tid & 1;
    const bool aval = (bm + arow) < M;
    const __half* Asrc = A + (size_t)(aval ? (bm + arow) : 0) * K + achk * 32;
    const uint32_t adst = sbase + arow * 144 + achk * 64;
    const int asz = aval ? 16 : 0;

    const __half* Bsrc = Bt + (size_t)(bn + tid) * K;
    const uint32_t bdst = sbase + PG_BBASE + tid * 144;

    const int nk = K / 64;

#define PG_ISSUE(kt, s)                                                         \
    {                                                                           \
        const __half* as_ = Asrc + (kt) * 64;                                   \
        uint32_t ad_ = adst + (s) * PG_ASTAGE_B;                                \
        cp16h(ad_,      as_,      asz); cp16h(ad_ + 16, as_ + 8,  asz);         \
        cp16h(ad_ + 32, as_ + 16, asz); cp16h(ad_ + 48, as_ + 24, asz);         \
        const __half* bs_ = Bsrc + (kt) * 64;                                   \
        uint32_t bd_ = bdst + (s) * PG_BSTAGE_B;                                \
        cp16h(bd_,       bs_,      16); cp16h(bd_ + 16,  bs_ + 8,  16);         \
        cp16h(bd_ + 32,  bs_ + 16, 16); cp16h(bd_ + 48,  bs_ + 24, 16);         \
        cp16h(bd_ + 64,  bs_ + 32, 16); cp16h(bd_ + 80,  bs_ + 40, 16);         \
        cp16h(bd_ + 96,  bs_ + 48, 16); cp16h(bd_ + 112, bs_ + 56, 16);         \
    }

#pragma unroll
    for (int s = 0; s < PG_STAGES - 1; s++) {
        PG_ISSUE(s, s);
        asm volatile("cp.async.commit_group;" ::: "memory");
    }

    for (int kt = 0; kt < nk; kt++) {
        const int buf = kt % PG_STAGES;
        asm volatile("cp.async.wait_group %0;" :: "n"(PG_STAGES - 2) : "memory");
        __syncthreads();

        const int nt = kt + PG_STAGES - 1;
        if (nt < nk) { PG_ISSUE(nt, nt % PG_STAGES); }
        asm volatile("cp.async.commit_group;" ::: "memory");

        const uint32_t* Aw = (const uint32_t*)(dsm + buf * PG_ASTAGE_B);
        const uint32_t* Bw = (const uint32_t*)(dsm + PG_BBASE + buf * PG_BSTAGE_B);
#pragma unroll
        for (int kk = 0; kk < 4; kk++) {
            const int kw = kk * 8 + tig;
            uint32_t bf0[8], bf1[8];
#pragma unroll
            for (int j = 0; j < 8; j++) {
                const int n0 = wn + j * 8 + g;
                bf0[j] = Bw[n0 * 36 + kw];
                bf1[j] = Bw[n0 * 36 + kw + 4];
            }
#pragma unroll
            for (int i = 0; i < 4; i++) {
                const int r = wm + i * 16 + g;
                uint32_t a0 = Aw[r * 36 + kw];
                uint32_t a1 = Aw[(r + 8) * 36 + kw];
                uint32_t a2 = Aw[r * 36 + kw + 4];
                uint32_t a3 = Aw[(r + 8) * 36 + kw + 4];
#pragma unroll
                for (int j = 0; j < 8; j++) {
                    asm volatile(
                        "mma.sync.aligned.m16n8k16.row.col.f32.f16.f16.f32 "
                        "{%0,%1,%2,%3}, {%4,%5,%6,%7}, {%8,%9}, {%0,%1,%2,%3};"
                        : "+f"(acc[i][j][0]), "+f"(acc[i][j][1]),
                          "+f"(acc[i][j][2]), "+f"(acc[i][j][3])
                        : "r"(a0), "r"(a1), "r"(a2), "r"(a3),
                          "r"(bf0[j]), "r"(bf1[j]));
                }
            }
        }
    }

#pragma unroll
    for (int i = 0; i < 4; i++) {
        const int r0 = bm + wm + i * 16 + g;
        const int r1 = r0 + 8;
#pragma unroll
        for (int j = 0; j < 8; j++) {
            const int col = bn + wn + j * 8 + 2 * tig;
            const float bv0 = bias[col];
            const float bv1 = bias[col + 1];
            float v0a = acc[i][j][0] + bv0;
            float v1a = acc[i][j][1] + bv1;
            float v2a = acc[i][j][2] + bv0;
            float v3a = acc[i][j][3] + bv1;
            if (ACT == 1) { v0a = gelu_f(v0a); v1a = gelu_f(v1a); v2a = gelu_f(v2a); v3a = gelu_f(v3a); }
            if (OUTHALF) {
                if (r0 < M) *(half2*)&C16[(size_t)r0 * N + col] = __floats2half2_rn(v0a, v1a);
                if (r1 < M) *(half2*)&C16[(size_t)r1 * N + col] = __floats2half2_rn(v2a, v3a);
            } else {
                if (r0 < M) *(float2*)&C[(size_t)r0 * N + col] = make_float2(v0a, v1a);
                if (r1 < M) *(float2*)&C[(size_t)r1 * N + col] = make_float2(v2a, v3a);
            }
        }
    }
}

// ---------------- assemble h (+fp16 copy) ----------------
__global__ void assemble_kernel(const float* __restrict__ x,
                                const float* __restrict__ rnd,
                                const int*   __restrict__ perm,
                                const float* __restrict__ mask_tok,
                                const float* __restrict__ agg_tok,
                                const float* __restrict__ pos_emb,
                                float* __restrict__ h, __half* __restrict__ h16,
                                float* __restrict__ mask_pos)
{
    int row = blockIdx.x;
    int b   = row / SEQ;
    int sp  = row - b * SEQ;
    int tid = threadIdx.x;
    float*  hp  = h   + (size_t)row * D_;
    __half* hp16 = h16 + (size_t)row * D_;

    if (sp == 0) {
#pragma unroll
        for (int e = 0; e < 3; e++) {
            int d = tid + e * 256;
            float v = agg_tok[d];
            hp[d] = v; hp16[d] = __float2half(v);
        }
        return;
    }
    int s = sp - 1;
    int i = b * S_ + s;
    float r0 = rnd[i * 3 + 0];
    float r1 = rnd[i * 3 + 1];
    float r2 = rnd[i * 3 + 2];
    bool  sel = (r0 <= 0.2f);
    float m  = (sel && r1 <= 0.8f) ? 1.f : 0.f;
    float rd = (sel && r1 > 0.8f && r2 <= 0.5f) ? 1.f : 0.f;
    if (tid == 0) mask_pos[i] = sel ? 1.f : 0.f;

    int pi = perm[i];
    const float* xp = x + (size_t)i  * D_;
    const float* sh = x + (size_t)pi * D_;
    const float* pe = pos_emb + (size_t)s * D_;
    float keep = 1.f - m - rd;

#pragma unroll
    for (int e = 0; e < 3; e++) {
        int d = tid + e * 256;
        float v = xp[d] * keep + mask_tok[d] * m + sh[d] * rd + pe[d];
        hp[d] = v; hp16[d] = __float2half(v);
    }
}

// ================= tensor-core flash attention =================
#define SP     288
#define KSTR   72
#define VSTR   296
#define ATTN_SMEM (SP*KSTR*2 + 64*VSTR*2)

__global__ void __launch_bounds__(256)
attn_kernel(const __half* __restrict__ qkv, __half* __restrict__ O16)
{
    extern __shared__ char asm_[];
    __half* Ks = (__half*)asm_;
    __half* Vt = (__half*)(asm_ + SP * KSTR * 2);

    const int hh = blockIdx.x;
    const int bb = blockIdx.y;
    const int tid = threadIdx.x;
    const int wid = tid >> 5;
    const int lane = tid & 31;
    const int g = lane >> 2;
    const int tig = lane & 3;
    const int brow = bb * SEQ;

    for (int idx = tid; idx < SEQ * 32; idx += 256) {
        int seq = idx >> 5, d2 = idx & 31;
        half2 v = *(const half2*)&qkv[(size_t)(brow + seq) * 2304 + 768 + hh * 64 + d2 * 2];
        *(half2*)&Ks[seq * KSTR + d2 * 2] = v;
    }
    for (int idx = tid; idx < 64 * 20; idx += 256) {
        int d = idx / 20, w = idx % 20;
        *(half2*)&Vt[d * VSTR + 256 + w * 2] = __floats2half2_rn(0.f, 0.f);
    }
    for (int idx = tid; idx < SEQ * 64; idx += 256) {
        int seq = idx >> 6, d = idx & 63;
        Vt[d * VSTR + seq] = qkv[(size_t)(brow + seq) * 2304 + 1536 + hh * 64 + d];
    }
    __syncthreads();

    const uint32_t* Kw = (const uint32_t*)Ks;
    const uint32_t* Vw = (const uint32_t*)Vt;

    for (int qt = wid; qt < 17; qt += 8) {
        int qr0 = qt * 16 + g;     if (qr0 > 256) qr0 = 256;
        int qr1 = qt * 16 + 8 + g; if (qr1 > 256) qr1 = 256;
        const __half* q0 = qkv + (size_t)(brow + qr0) * 2304 + hh * 64;
        const __half* q1 = qkv + (size_t)(brow + qr1) * 2304 + hh * 64;
        uint32_t aq[4][4];
#pragma unroll
        for (int kc = 0; kc < 4; kc++) {
            int cb = kc * 16 + 2 * tig;
            aq[kc][0] = *(const uint32_t*)(q0 + cb);
            aq[kc][1] = *(const uint32_t*)(q1 + cb);
            aq[kc][2] = *(const uint32_t*)(q0 + cb + 8);
            aq[kc][3] = *(const uint32_t*)(q1 + cb + 8);
        }

        float m0 = -1e30f, m1 = -1e30f, l0 = 0.f, l1 = 0.f;
        float o[8][4];
#pragma unroll
        for (int nt = 0; nt < 8; nt++)
#pragma unroll
            for (int c = 0; c < 4; c++) o[nt][c] = 0.f;

#pragma unroll
        for (int ch = 0; ch < 2; ch++) {
            float sc[18][4];
#pragma unroll
            for (int j = 0; j < 18; j++)
#pragma unroll
                for (int c = 0; c < 4; c++) sc[j][c] = 0.f;

#pragma unroll
            for (int j = 0; j < 18; j++) {
                const int n0 = ch * 144 + j * 8 + g;
#pragma unroll
                for (int kc = 0; kc < 4; kc++) {
                    uint32_t b0 = Kw[n0 * (KSTR / 2) + kc * 8 + tig];
                    uint32_t b1 = Kw[n0 * (KSTR / 2) + kc * 8 + tig + 4];
                    asm volatile(
                        "mma.sync.aligned.m16n8k16.row.col.f32.f16.f16.f32 "
                        "{%0,%1,%2,%3}, {%4,%5,%6,%7}, {%8,%9}, {%0,%1,%2,%3};"
                        : "+f"(sc[j][0]), "+f"(sc[j][1]), "+f"(sc[j][2]), "+f"(sc[j][3])
                        : "r"(aq[kc][0]), "r"(aq[kc][1]), "r"(aq[kc][2]), "r"(aq[kc][3]),
                          "r"(b0), "r"(b1));
                }
            }

            float mx0 = -1e30f, mx1 = -1e30f;
#pragma unroll
            for (int j = 0; j < 18; j++) {
                int c0 = ch * 144 + j * 8 + 2 * tig;
                sc[j][0] = (c0     < SEQ) ? sc[j][0] * 0.125f : -1e30f;
                sc[j][1] = (c0 + 1 < SEQ) ? sc[j][1] * 0.125f : -1e30f;
                sc[j][2] = (c0     < SEQ) ? sc[j][2] * 0.125f : -1e30f;
                sc[j][3] = (c0 + 1 < SEQ) ? sc[j][3] * 0.125f : -1e30f;
                mx0 = fmaxf(mx0, fmaxf(sc[j][0], sc[j][1]));
                mx1 = fmaxf(mx1, fmaxf(sc[j][2], sc[j][3]));
            }
            mx0 = fmaxf(mx0, __shfl_xor_sync(0xffffffffu, mx0, 1));
            mx0 = fmaxf(mx0, __shfl_xor_sync(0xffffffffu, mx0, 2));
            mx1 = fmaxf(mx1, __shfl_xor_sync(0xffffffffu, mx1, 1));
            mx1 = fmaxf(mx1, __shfl_xor_sync(0xffffffffu, mx1, 2));

            float mn0 = fmaxf(m0, mx0), mn1 = fmaxf(m1, mx1);
            float sc0 = __expf(m0 - mn0), sc1 = __expf(m1 - mn1);
            m0 = mn0; m1 = mn1;

            float sum0 = 0.f, sum1 = 0.f;
#pragma unroll
            for (int j = 0; j < 18; j++) {
                sc[j][0] = __expf(sc[j][0] - mn0);
                sc[j][1] = __expf(sc[j][1] - mn0);
                sc[j][2] = __expf(sc[j][2] - mn1);
                sc[j][3] = __expf(sc[j][3] - mn1);
                sum0 += sc[j][0] + sc[j][1];
                sum1 += sc[j][2] + sc[j][3];
            }
            sum0 += __shfl_xor_sync(0xffffffffu, sum0, 1);
            sum0 += __shfl_xor_sync(0xffffffffu, sum0, 2);
            sum1 += __shfl_xor_sync(0xffffffffu, sum1, 1);
            sum1 += __shfl_xor_sync(0xffffffffu, sum1, 2);
            l0 = l0 * sc0 + sum0;
            l1 = l1 * sc1 + sum1;

#pragma unroll
            for (int nt = 0; nt < 8; nt++) {
                o[nt][0] *= sc0; o[nt][1] *= sc0;
                o[nt][2] *= sc1; o[nt][3] *= sc1;
            }

#pragma unroll
            for (int kc = 0; kc < 9; kc++) {
                half2 pa0 = __floats2half2_rn(sc[2*kc][0],   sc[2*kc][1]);
                half2 pa1 = __floats2half2_rn(sc[2*kc][2],   sc[2*kc][3]);
                half2 pa2 = __floats2half2_rn(sc[2*kc+1][0], sc[2*kc+1][1]);
                half2 pa3 = __floats2half2_rn(sc[2*kc+1][2], sc[2*kc+1][3]);
                uint32_t ua0 = *(uint32_t*)&pa0, ua1 = *(uint32_t*)&pa1;
                uint32_t ua2 = *(uint32_t*)&pa2, ua3 = *(uint32_t*)&pa3;
                const int kb2 = (ch * 144 + kc * 16) / 2;
#pragma unroll
                for (int nt = 0; nt < 8; nt++) {
                    const int vr = nt * 8 + g;
                    uint32_t b0 = Vw[vr * (VSTR / 2) + kb2 + tig];
                    uint32_t b1 = Vw[vr * (VSTR / 2) + kb2 + tig + 4];
                    asm volatile(
                        "mma.sync.aligned.m16n8k16.row.col.f32.f16.f16.f32 "
                        "{%0,%1,%2,%3}, {%4,%5,%6,%7}, {%8,%9}, {%0,%1,%2,%3};"
                        : "+f"(o[nt][0]), "+f"(o[nt][1]), "+f"(o[nt][2]), "+f"(o[nt][3])
                        : "r"(ua0), "r"(ua1), "r"(ua2), "r"(ua3),
                          "r"(b0), "r"(b1));
                }
            }
        }

        float inv0 = 1.f / l0, inv1 = 1.f / l1;
        int r0 = qt * 16 + g, r1 = r0 + 8;
#pragma unroll
        for (int nt = 0; nt < 8; nt++) {
            int col = hh * 64 + nt * 8 + 2 * tig;
            if (r0 < SEQ)
                *(half2*)&O16[(size_t)(brow + r0) * 768 + col] =
                    __floats2half2_rn(o[nt][0] * inv0, o[nt][1] * inv0);
            if (r1 < SEQ)
                *(half2*)&O16[(size_t)(brow + r1) * 768 + col] =
                    __floats2half2_rn(o[nt][2] * inv1, o[nt][3] * inv1);
        }
    }
}

// ---------------- residual + LayerNorm (fp16 delta) ----------------
template<int OUT>
__global__ void add_ln_kernel(const float* __restrict__ H, const __half* __restrict__ Dl,
                              const float* __restrict__ g, const float* __restrict__ be,
                              float* __restrict__ Out, __half* __restrict__ Out16,
                              float* __restrict__ Pred)
{
    int row = blockIdx.x, tid = threadIdx.x;
    const float*  hp = H  + (size_t)row * D_;
    const __half* dp = Dl + (size_t)row * D_;
    float v0 = hp[tid]       + __half2float(dp[tid]);
    float v1 = hp[tid + 256] + __half2float(dp[tid + 256]);
    float v2 = hp[tid + 512] + __half2float(dp[tid + 512]);

    __shared__ float red[8];
    __shared__ float s_mu, s_var;
    int lane = tid & 31, w = tid >> 5;

    float s = v0 + v1 + v2;
    for (int off = 16; off; off >>= 1) s += __shfl_xor_sync(0xffffffffu, s, off);
    if (lane == 0) red[w] = s;
    __syncthreads();
    if (tid == 0) {
        float t = 0.f;
        for (int i = 0; i < 8; i++) t += red[i];
        s_mu = t * (1.0f / 768.0f);
    }
    __syncthreads();
    float mu = s_mu;
    float d0 = v0 - mu, d1 = v1 - mu, d2 = v2 - mu;
    float qv = d0 * d0 + d1 * d1 + d2 * d2;
    for (int off = 16; off; off >>= 1) qv += __shfl_xor_sync(0xffffffffu, qv, off);
    if (lane == 0) red[w] = qv;
    __syncthreads();
    if (tid == 0) {
        float t = 0.f;
        for (int i = 0; i < 8; i++) t += red[i];
        s_var = t * (1.0f / 768.0f);
    }
    __syncthreads();
    float rs = rsqrtf(s_var + 1e-6f);

    float o0 = d0 * rs * g[tid]       + be[tid];
    float o1 = d1 * rs * g[tid + 256] + be[tid + 256];
    float o2 = d2 * rs * g[tid + 512] + be[tid + 512];

    if (OUT == 0) {
        float*  op   = Out   + (size_t)row * D_;
        __half* op16 = Out16 + (size_t)row * D_;
        op[tid] = o0;        op16[tid] = __float2half(o0);
        op[tid + 256] = o1;  op16[tid + 256] = __float2half(o1);
        op[tid + 512] = o2;  op16[tid + 512] = __float2half(o2);
    } else {
        int b  = row / SEQ;
        int sp = row - b * SEQ;
        float* op = (sp == 0) ? (Out + (size_t)b * D_)
                              : (Pred + (size_t)(b * S_ + sp - 1) * D_);
        op[tid] = o0; op[tid + 256] = o1; op[tid + 512] = o2;
    }
}

// ---------------- host ----------------
static inline void run_hgemm(const __half* A, const __half* Bt, const float* bias,
                             float* C, __half* C16, int M, int N, int K, int mode)
{
    dim3 grid(N / 256, (M + 127) / 128);
    if (mode == 2)      hgemm_kernel<1, 1><<<grid, 256, PG_SMEM>>>(A, Bt, bias, C, C16, M, N, K);
    else if (mode == 1) hgemm_kernel<0, 1><<<grid, 256, PG_SMEM>>>(A, Bt, bias, C, C16, M, N, K);
    else                hgemm_kernel<0, 0><<<grid, 256, PG_SMEM>>>(A, Bt, bias, C, C16, M, N, K);
}

extern "C" void kernel_launch(void* const* d_in, const int* in_sizes, int n_in,
                              void* d_out, int out_size)
{
    const float* inputs     = (const float*)d_in[0];
    const float* randomness = (const float*)d_in[1];
    const int*   perm       = (const int*)  d_in[2];
    const float* conv_w     = (const float*)d_in[3];
    const float* conv_b     = (const float*)d_in[4];
    const float* pos_emb    = (const float*)d_in[5];
    const float* mask_tok   = (const float*)d_in[6];
    const float* agg_tok    = (const float*)d_in[7];
    const float* wq  = (const float*)d_in[8];
    const float* bq  = (const float*)d_in[9];
    const float* wk  = (const float*)d_in[10];
    const float* bk  = (const float*)d_in[11];
    const float* wv  = (const float*)d_in[12];
    const float* bv  = (const float*)d_in[13];
    const float* wo  = (const float*)d_in[14];
    const float* bo  = (const float*)d_in[15];
    const float* ln1g = (const float*)d_in[16];
    const float* ln1b = (const float*)d_in[17];
    const float* w1  = (const float*)d_in[18];
    const float* b1  = (const float*)d_in[19];
    const float* w2  = (const float*)d_in[20];
    const float* b2  = (const float*)d_in[21];
    const float* ln2g = (const float*)d_in[22];
    const float* ln2b = (const float*)d_in[23];

    float* out      = (float*)d_out;
    float* out_agg  = out;
    float* out_pred = out + 49152;
    float* out_mask = out + 12632064;
    float* out_emb  = out + 12648448;

    float *h, *biasqkv;
    __half *h16, *t16, *o16, *f16, *qkv16, *in16, *wt;
    cudaGetSymbolAddress((void**)&h,  g_h);
    cudaGetSymbolAddress((void**)&h16, g_h16);
    cudaGetSymbolAddress((void**)&t16, g_t16);
    cudaGetSymbolAddress((void**)&o16, g_o16);
    cudaGetSymbolAddress((void**)&f16, g_f16);
    cudaGetSymbolAddress((void**)&qkv16, g_qkv16);
    cudaGetSymbolAddress((void**)&in16, g_in16);
    cudaGetSymbolAddress((void**)&wt,  g_wt);
    cudaGetSymbolAddress((void**)&biasqkv, g_biasqkv);

    cudaFuncSetAttribute(hgemm_kernel<0,0>, cudaFuncAttributeMaxDynamicSharedMemorySize, PG_SMEM);
    cudaFuncSetAttribute(hgemm_kernel<0,1>, cudaFuncAttributeMaxDynamicSharedMemorySize, PG_SMEM);
    cudaFuncSetAttribute(hgemm_kernel<1,1>, cudaFuncAttributeMaxDynamicSharedMemorySize, PG_SMEM);
    cudaFuncSetAttribute(attn_kernel, cudaFuncAttributeMaxDynamicSharedMemorySize, ATTN_SMEM);

    // prep (z-batched)
    in16_kernel<<<8192, 256>>>(inputs, in16, 2097152);
    biascat_kernel<<<2, 256>>>(bq, bk, bv, biasqkv);
    {
        dim3 blk(32, 8);
        wt16_kernel<<<dim3(24, 16, 1), blk>>>(conv_w, wt + CW_OFF, 512, 768, 0, 0);
        wt16_kernel<<<dim3(24, 24, 2), blk>>>(wq, wt + QKV_OFF,           768, 768, 589824, 1769472);
        wt16_kernel<<<dim3(24, 24, 2), blk>>>(wk, wt + QKV_OFF + 589824,  768, 768, 589824, 1769472);
        wt16_kernel<<<dim3(24, 24, 2), blk>>>(wv, wt + QKV_OFF + 1179648, 768, 768, 589824, 1769472);
        wt16_kernel<<<dim3(24, 24, 2), blk>>>(wo, wt + WO_OFF,            768, 768, 589824, 589824);
        wt16_kernel<<<dim3(96, 24, 2), blk>>>(w1, wt + W1_OFF,            768, 3072, 2359296, 2359296);
        wt16_kernel<<<dim3(24, 96, 2), blk>>>(w2, wt + W2_OFF,            3072, 768, 2359296, 2359296);
    }

    // conv as GEMM, writes embeddings output directly
    run_hgemm(in16, wt + CW_OFF, conv_b, out_emb, nullptr, BSR, D_, 512, 0);

    assemble_kernel<<<ROWS, 256>>>(out_emb, randomness, perm, mask_tok, agg_tok,
                                   pos_emb, h, h16, out_mask);

    for (int l = 0; l < 2; l++) {
        const __half* qkvw = wt + QKV_OFF + (size_t)l * 1769472;
        const __half* wo_t = wt + WO_OFF + (size_t)l * 589824;
        const __half* w1_t = wt + W1_OFF + (size_t)l * 2359296;
        const __half* w2_t = wt + W2_OFF + (size_t)l * 2359296;

        run_hgemm(h16, qkvw, biasqkv + l * 2304, nullptr, qkv16, ROWS, 2304, D_, 1);

        attn_kernel<<<dim3(HEADS, B_), 256, ATTN_SMEM>>>(qkv16, o16);

        run_hgemm(o16, wo_t, bo + l * D_, nullptr, t16, ROWS, D_, D_, 1);
        add_ln_kernel<0><<<ROWS, 256>>>(h, t16, ln1g + l * D_, ln1b + l * D_, h, h16, nullptr);

        run_hgemm(h16, w1_t, b1 + l * F_, nullptr, f16, ROWS, F_, D_, 2);
        run_hgemm(f16, w2_t, b2 + l * D_, nullptr, t16, ROWS, D_, F_, 1);
        if (l == 0)
            add_ln_kernel<0><<<ROWS, 256>>>(h, t16, ln2g + l * D_, ln2b + l * D_, h, h16, nullptr);
        else
            add_ln_kernel<1><<<ROWS, 256>>>(h, t16, ln2g + l * D_, ln2b + l * D_, out_agg, nullptr, out_pred);
    }
}